// round 1
// baseline (speedup 1.0000x reference)
#include <cuda_runtime.h>
#include <cstddef>

// Problem constants
#define B_ 2
#define S_ 4096
#define D_ 512
#define H_ 8
#define DH_ 64

// ---------------- scratch (no allocation allowed) ----------------
__device__ float g_q[(size_t)B_ * S_ * D_];
__device__ float g_k[(size_t)B_ * S_ * D_];
__device__ float g_v[(size_t)B_ * S_ * D_];
__device__ float g_o[(size_t)B_ * S_ * D_];

// ---------------- fast exp2 on the FMA pipe ----------------
__device__ __forceinline__ float exp2_fast(float x) {
    // x <= 0 always (score - running max). Clamp to avoid denormal garbage.
    x = fmaxf(x, -120.0f);
    float r = rintf(x);
    float f = x - r;                 // f in [-0.5, 0.5]
    float p = 1.3333558e-3f;
    p = fmaf(p, f, 9.6181291e-3f);
    p = fmaf(p, f, 5.5504109e-2f);
    p = fmaf(p, f, 2.4022651e-1f);
    p = fmaf(p, f, 6.9314718e-1f);
    p = fmaf(p, f, 1.0f);            // 2^f, ~2e-6 abs err
    int i = (int)r;
    return __int_as_float(__float_as_int(p) + (i << 23));
}

// ---------------- GEMM: C = relu(A[M,K] @ B[K,N] + bias) ----------------
// 128x128 tile, BK=8, 256 threads, 8x8 per thread.
#define GM 128
#define GN 128
#define GK 8

__global__ void __launch_bounds__(256)
gemm_bias_relu(const float* __restrict__ A, const float* __restrict__ Bm,
               const float* __restrict__ bias, float* __restrict__ C,
               int M, int N, int K)
{
    __shared__ float As[GK][GM];  // A transposed: As[k][m]
    __shared__ float Bs[GK][GN];

    const int tid = threadIdx.x;
    const int bm = blockIdx.y * GM;
    const int bn = blockIdx.x * GN;
    const int ty = tid >> 4;          // 0..15 -> row group
    const int tx = tid & 15;          // 0..15 -> col group

    // A tile load mapping: 128 rows x 8 k, one float4 per thread
    const int ar = tid >> 1;           // 0..127
    const int ak = (tid & 1) * 4;      // 0 or 4
    // B tile load mapping: 8 k rows x 128 n, one float4 per thread
    const int bk = tid >> 5;           // 0..7
    const int bn4 = (tid & 31) * 4;    // 0..124

    float acc[8][8];
    #pragma unroll
    for (int i = 0; i < 8; i++)
        #pragma unroll
        for (int j = 0; j < 8; j++) acc[i][j] = 0.0f;

    for (int k0 = 0; k0 < K; k0 += GK) {
        float4 av = *(const float4*)(A + (size_t)(bm + ar) * K + k0 + ak);
        float4 bv = *(const float4*)(Bm + (size_t)(k0 + bk) * N + bn + bn4);
        __syncthreads();
        As[ak + 0][ar] = av.x;
        As[ak + 1][ar] = av.y;
        As[ak + 2][ar] = av.z;
        As[ak + 3][ar] = av.w;
        *(float4*)&Bs[bk][bn4] = bv;
        __syncthreads();

        #pragma unroll
        for (int k = 0; k < GK; k++) {
            float a0[8], b0[8];
            *(float4*)&a0[0] = *(const float4*)&As[k][ty * 8];
            *(float4*)&a0[4] = *(const float4*)&As[k][ty * 8 + 4];
            *(float4*)&b0[0] = *(const float4*)&Bs[k][tx * 8];
            *(float4*)&b0[4] = *(const float4*)&Bs[k][tx * 8 + 4];
            #pragma unroll
            for (int i = 0; i < 8; i++)
                #pragma unroll
                for (int j = 0; j < 8; j++)
                    acc[i][j] = fmaf(a0[i], b0[j], acc[i][j]);
        }
    }

    float bb[8];
    #pragma unroll
    for (int j = 0; j < 8; j++) bb[j] = bias[bn + tx * 8 + j];

    #pragma unroll
    for (int i = 0; i < 8; i++) {
        const int row = bm + ty * 8 + i;
        float4 o0, o1;
        o0.x = fmaxf(acc[i][0] + bb[0], 0.0f);
        o0.y = fmaxf(acc[i][1] + bb[1], 0.0f);
        o0.z = fmaxf(acc[i][2] + bb[2], 0.0f);
        o0.w = fmaxf(acc[i][3] + bb[3], 0.0f);
        o1.x = fmaxf(acc[i][4] + bb[4], 0.0f);
        o1.y = fmaxf(acc[i][5] + bb[5], 0.0f);
        o1.z = fmaxf(acc[i][6] + bb[6], 0.0f);
        o1.w = fmaxf(acc[i][7] + bb[7], 0.0f);
        *(float4*)(C + (size_t)row * N + bn + tx * 8)     = o0;
        *(float4*)(C + (size_t)row * N + bn + tx * 8 + 4) = o1;
    }
}

// ---------------- Flash attention ----------------
// 128 q-rows per block, 1 row per thread. K/V tiles 64xDH in smem.
// All arithmetic in log2 domain: q is pre-scaled by (1/sqrt(DH))*log2(e).
#define AT_BM 128
#define AT_BN 64
// smem floats: Ks 64*64 + Vs 64*64 + Ss 128*(64+1)
#define ATTN_SMEM_FLOATS (2 * AT_BN * DH_ + AT_BM * (AT_BN + 1))

__global__ void __launch_bounds__(128)
attn_kernel(const float* __restrict__ Q, const float* __restrict__ K,
            const float* __restrict__ V, float* __restrict__ O)
{
    extern __shared__ float sm[];
    float* Ks = sm;                       // [AT_BN][DH]
    float* Vs = sm + AT_BN * DH_;         // [AT_BN][DH]
    float* Ss = sm + 2 * AT_BN * DH_;     // [AT_BM][AT_BN+1]

    const int tid = threadIdx.x;
    const int qblk = blockIdx.x;
    const int h = blockIdx.y;
    const int b = blockIdx.z;
    const int row = qblk * AT_BM + tid;

    const float scale = 0.125f * 1.44269504f;  // 1/sqrt(64) * log2(e)

    const float* qp = Q + ((size_t)b * S_ + row) * D_ + h * DH_;
    float q[DH_];
    #pragma unroll
    for (int d = 0; d < DH_; d += 4) {
        float4 t = *(const float4*)(qp + d);
        q[d + 0] = t.x * scale;
        q[d + 1] = t.y * scale;
        q[d + 2] = t.z * scale;
        q[d + 3] = t.w * scale;
    }

    float acc[DH_];
    #pragma unroll
    for (int d = 0; d < DH_; d++) acc[d] = 0.0f;
    float m = -1e30f, l = 0.0f;

    const size_t kvbase = (size_t)b * S_ * D_ + h * DH_;

    for (int t0 = 0; t0 < S_; t0 += AT_BN) {
        __syncthreads();  // previous-tile consumers done before overwrite
        // load K/V tiles: 64 rows x 16 float4 each
        for (int i = tid; i < AT_BN * 16; i += AT_BM) {
            int j = i >> 4, d4 = (i & 15) * 4;
            size_t goff = kvbase + (size_t)(t0 + j) * D_ + d4;
            *(float4*)&Ks[j * DH_ + d4] = *(const float4*)(K + goff);
            *(float4*)&Vs[j * DH_ + d4] = *(const float4*)(V + goff);
        }
        __syncthreads();

        // scores for this thread's row (smem reads are warp-uniform broadcasts)
        float tmax = -1e30f;
        #pragma unroll 4
        for (int j = 0; j < AT_BN; j++) {
            float s0 = 0.f, s1 = 0.f, s2 = 0.f, s3 = 0.f;
            const float* kr = &Ks[j * DH_];
            #pragma unroll
            for (int d = 0; d < DH_; d += 4) {
                s0 = fmaf(q[d + 0], kr[d + 0], s0);
                s1 = fmaf(q[d + 1], kr[d + 1], s1);
                s2 = fmaf(q[d + 2], kr[d + 2], s2);
                s3 = fmaf(q[d + 3], kr[d + 3], s3);
            }
            float s = (s0 + s1) + (s2 + s3);
            Ss[tid * (AT_BN + 1) + j] = s;
            tmax = fmaxf(tmax, s);
        }

        float mnew = fmaxf(m, tmax);
        float corr = exp2_fast(m - mnew);
        l *= corr;
        #pragma unroll
        for (int d = 0; d < DH_; d++) acc[d] *= corr;
        m = mnew;

        #pragma unroll 2
        for (int j = 0; j < AT_BN; j++) {
            float p = exp2_fast(Ss[tid * (AT_BN + 1) + j] - m);
            l += p;
            const float* vr = &Vs[j * DH_];
            #pragma unroll
            for (int d = 0; d < DH_; d++)
                acc[d] = fmaf(p, vr[d], acc[d]);
        }
    }

    const float inv = 1.0f / l;
    float* op = O + ((size_t)b * S_ + row) * D_ + h * DH_;
    #pragma unroll
    for (int d = 0; d < DH_; d += 4) {
        float4 o;
        o.x = acc[d + 0] * inv;
        o.y = acc[d + 1] * inv;
        o.z = acc[d + 2] * inv;
        o.w = acc[d + 3] * inv;
        *(float4*)(op + d) = o;
    }
}

// ---------------- launch ----------------
extern "C" void kernel_launch(void* const* d_in, const int* in_sizes, int n_in,
                              void* d_out, int out_size)
{
    const float* x  = (const float*)d_in[0];
    const float* Wq = (const float*)d_in[1];
    const float* bq = (const float*)d_in[2];
    const float* Wk = (const float*)d_in[3];
    const float* bk = (const float*)d_in[4];
    const float* Wv = (const float*)d_in[5];
    const float* bv = (const float*)d_in[6];
    const float* Wo = (const float*)d_in[7];
    const float* bo = (const float*)d_in[8];
    float* out = (float*)d_out;

    float *Qb, *Kb, *Vb, *Ob;
    cudaGetSymbolAddress((void**)&Qb, g_q);
    cudaGetSymbolAddress((void**)&Kb, g_k);
    cudaGetSymbolAddress((void**)&Vb, g_v);
    cudaGetSymbolAddress((void**)&Ob, g_o);

    const int M = B_ * S_;   // 8192
    const int N = D_;        // 512
    const int K = D_;        // 512

    dim3 ggrid(N / GN, M / GM);   // (4, 64)
    gemm_bias_relu<<<ggrid, 256>>>(x, Wq, bq, Qb, M, N, K);
    gemm_bias_relu<<<ggrid, 256>>>(x, Wk, bk, Kb, M, N, K);
    gemm_bias_relu<<<ggrid, 256>>>(x, Wv, bv, Vb, M, N, K);

    const int attn_smem = ATTN_SMEM_FLOATS * (int)sizeof(float);  // 66048 B
    cudaFuncSetAttribute(attn_kernel, cudaFuncAttributeMaxDynamicSharedMemorySize,
                         attn_smem);
    dim3 agrid(S_ / AT_BM, H_, B_);  // (32, 8, 2)
    attn_kernel<<<agrid, AT_BM, attn_smem>>>(Qb, Kb, Vb, Ob);

    gemm_bias_relu<<<ggrid, 256>>>(Ob, Wo, bo, out, M, N, K);
}

// round 2
// speedup vs baseline: 1.3484x; 1.3484x over previous
#include <cuda_runtime.h>
#include <cstddef>

// Problem constants
#define B_ 2
#define S_ 4096
#define D_ 512
#define H_ 8
#define DH_ 64

// ---------------- scratch (no allocation allowed) ----------------
__device__ float g_q[(size_t)B_ * S_ * D_];
__device__ float g_k[(size_t)B_ * S_ * D_];
__device__ float g_v[(size_t)B_ * S_ * D_];
__device__ float g_o[(size_t)B_ * S_ * D_];

// ---------------- fast exp2 on the FMA pipe ----------------
__device__ __forceinline__ float exp2_fast(float x) {
    x = fmaxf(x, -120.0f);
    float r = rintf(x);
    float f = x - r;                 // f in [-0.5, 0.5]
    float p = 1.3333558e-3f;
    p = fmaf(p, f, 9.6181291e-3f);
    p = fmaf(p, f, 5.5504109e-2f);
    p = fmaf(p, f, 2.4022651e-1f);
    p = fmaf(p, f, 6.9314718e-1f);
    p = fmaf(p, f, 1.0f);            // 2^f, ~2e-6 abs err
    int i = (int)r;
    return __int_as_float(__float_as_int(p) + (i << 23));
}

// ================= GEMM: C = relu(A[M,K] @ W[K,N] + bias) =================
// 128x128 tile, GK=16, 256 threads, 8x8 per thread, register prefetch.
#define GM 128
#define GN 128
#define GK 16
#define AS_STRIDE 132

__device__ __forceinline__ void gemm_body(
    const float* __restrict__ A, const float* __restrict__ W,
    const float* __restrict__ bias, float* __restrict__ C,
    int M, int N, int K, int bm, int bn)
{
    __shared__ float As[GK][AS_STRIDE];  // A transposed: As[k][m]
    __shared__ float Bs[GK][GN];

    const int tid = threadIdx.x;
    const int ty = tid >> 4;          // 0..15
    const int tx = tid & 15;          // 0..15

    const int ar = tid >> 1;           // 0..127
    const int ak = (tid & 1) * 8;      // 0 or 8
    const int bk = tid >> 4;           // 0..15
    const int bn8 = (tid & 15) * 8;    // 0..120

    float acc[8][8];
    #pragma unroll
    for (int i = 0; i < 8; i++)
        #pragma unroll
        for (int j = 0; j < 8; j++) acc[i][j] = 0.0f;

    // preload tile 0
    float4 a0 = *(const float4*)(A + (size_t)(bm + ar) * K + ak);
    float4 a1 = *(const float4*)(A + (size_t)(bm + ar) * K + ak + 4);
    float4 w0 = *(const float4*)(W + (size_t)bk * N + bn + bn8);
    float4 w1 = *(const float4*)(W + (size_t)bk * N + bn + bn8 + 4);

    for (int k0 = 0; k0 < K; k0 += GK) {
        __syncthreads();
        As[ak + 0][ar] = a0.x; As[ak + 1][ar] = a0.y;
        As[ak + 2][ar] = a0.z; As[ak + 3][ar] = a0.w;
        As[ak + 4][ar] = a1.x; As[ak + 5][ar] = a1.y;
        As[ak + 6][ar] = a1.z; As[ak + 7][ar] = a1.w;
        *(float4*)&Bs[bk][bn8]     = w0;
        *(float4*)&Bs[bk][bn8 + 4] = w1;
        __syncthreads();

        if (k0 + GK < K) {  // prefetch next tile (overlaps with math below)
            a0 = *(const float4*)(A + (size_t)(bm + ar) * K + k0 + GK + ak);
            a1 = *(const float4*)(A + (size_t)(bm + ar) * K + k0 + GK + ak + 4);
            w0 = *(const float4*)(W + (size_t)(k0 + GK + bk) * N + bn + bn8);
            w1 = *(const float4*)(W + (size_t)(k0 + GK + bk) * N + bn + bn8 + 4);
        }

        #pragma unroll
        for (int k = 0; k < GK; k++) {
            float av[8], bv[8];
            *(float4*)&av[0] = *(const float4*)&As[k][ty * 8];
            *(float4*)&av[4] = *(const float4*)&As[k][ty * 8 + 4];
            *(float4*)&bv[0] = *(const float4*)&Bs[k][tx * 8];
            *(float4*)&bv[4] = *(const float4*)&Bs[k][tx * 8 + 4];
            #pragma unroll
            for (int i = 0; i < 8; i++)
                #pragma unroll
                for (int j = 0; j < 8; j++)
                    acc[i][j] = fmaf(av[i], bv[j], acc[i][j]);
        }
    }

    float bb[8];
    #pragma unroll
    for (int j = 0; j < 8; j++) bb[j] = bias[bn + tx * 8 + j];

    #pragma unroll
    for (int i = 0; i < 8; i++) {
        const int row = bm + ty * 8 + i;
        float4 o0, o1;
        o0.x = fmaxf(acc[i][0] + bb[0], 0.0f);
        o0.y = fmaxf(acc[i][1] + bb[1], 0.0f);
        o0.z = fmaxf(acc[i][2] + bb[2], 0.0f);
        o0.w = fmaxf(acc[i][3] + bb[3], 0.0f);
        o1.x = fmaxf(acc[i][4] + bb[4], 0.0f);
        o1.y = fmaxf(acc[i][5] + bb[5], 0.0f);
        o1.z = fmaxf(acc[i][6] + bb[6], 0.0f);
        o1.w = fmaxf(acc[i][7] + bb[7], 0.0f);
        *(float4*)(C + (size_t)row * N + bn + tx * 8)     = o0;
        *(float4*)(C + (size_t)row * N + bn + tx * 8 + 4) = o1;
    }
}

// fused Q/K/V projection: blockIdx.z selects which projection
__global__ void __launch_bounds__(256)
gemm_qkv(const float* __restrict__ x,
         const float* __restrict__ Wq, const float* __restrict__ bq, float* __restrict__ Q,
         const float* __restrict__ Wk, const float* __restrict__ bk, float* __restrict__ K,
         const float* __restrict__ Wv, const float* __restrict__ bv, float* __restrict__ V)
{
    const float* W; const float* bias; float* C;
    if (blockIdx.z == 0)      { W = Wq; bias = bq; C = Q; }
    else if (blockIdx.z == 1) { W = Wk; bias = bk; C = K; }
    else                      { W = Wv; bias = bv; C = V; }
    gemm_body(x, W, bias, C, B_ * S_, D_, D_, blockIdx.y * GM, blockIdx.x * GN);
}

__global__ void __launch_bounds__(256)
gemm_single(const float* __restrict__ A, const float* __restrict__ W,
            const float* __restrict__ bias, float* __restrict__ C)
{
    gemm_body(A, W, bias, C, B_ * S_, D_, D_, blockIdx.y * GM, blockIdx.x * GN);
}

// ================= Flash attention (register-tiled) =================
// BM=128 q-rows, BN=64 keys per tile, 256 threads.
// Micro-tile 8 rows x 4 cols per thread for both S=QK^T and O+=PV.
#define AT_BM 128
#define AT_BN 64
#define QST_STRIDE 132
#define KST_STRIDE 68
// smem floats: Qst 64x132 + Kst 64x68 + Vs 64x68 + Pst 64x132
#define ATTN_SMEM_FLOATS (DH_ * QST_STRIDE + AT_BN * KST_STRIDE + AT_BN * KST_STRIDE + AT_BN * QST_STRIDE)

__global__ void __launch_bounds__(256)
attn_kernel(const float* __restrict__ Q, const float* __restrict__ K,
            const float* __restrict__ V, float* __restrict__ O)
{
    extern __shared__ float sm[];
    float* Qst = sm;                                   // [DH][132] (d-major)
    float* Kst = Qst + DH_ * QST_STRIDE;               // [DH][68]  (d-major)
    float* Vs  = Kst + AT_BN * KST_STRIDE;             // [BN][68]  (n-major)
    float* Pst = Vs  + AT_BN * KST_STRIDE;             // [BN][132] (n-major)

    const int tid = threadIdx.x;
    const int tm = tid >> 4;   // 0..15, row group (8 rows)
    const int tn = tid & 15;   // 0..15, col group (4 cols)
    const int qblk = blockIdx.x;
    const int h = blockIdx.y;
    const int b = blockIdx.z;

    const float scale = 0.125f * 1.44269504f;  // 1/sqrt(64) * log2(e)

    // ---- prologue: load Q tile [128][64] transposed into Qst[d][m], pre-scaled
    {
        const float* qbase = Q + ((size_t)b * S_ + qblk * AT_BM) * D_ + h * DH_;
        #pragma unroll
        for (int it = 0; it < 8; it++) {
            int idx = tid + it * 256;        // 0..2047
            int mrow = idx >> 4;             // 0..127
            int d4 = (idx & 15) * 4;         // 0..60
            float4 t = *(const float4*)(qbase + (size_t)mrow * D_ + d4);
            Qst[(d4 + 0) * QST_STRIDE + mrow] = t.x * scale;
            Qst[(d4 + 1) * QST_STRIDE + mrow] = t.y * scale;
            Qst[(d4 + 2) * QST_STRIDE + mrow] = t.z * scale;
            Qst[(d4 + 3) * QST_STRIDE + mrow] = t.w * scale;
        }
    }

    float o[8][4];
    float m[8], l[8];
    #pragma unroll
    for (int i = 0; i < 8; i++) {
        m[i] = -1e30f; l[i] = 0.0f;
        #pragma unroll
        for (int j = 0; j < 4; j++) o[i][j] = 0.0f;
    }

    const size_t kvbase = (size_t)b * S_ * D_ + h * DH_;

    for (int t0 = 0; t0 < S_; t0 += AT_BN) {
        __syncthreads();   // prev PV reads of Vs/Pst done before overwrite

        // load K tile transposed -> Kst[d][n]; V tile direct -> Vs[n][d]
        #pragma unroll
        for (int it = 0; it < 4; it++) {
            int idx = tid + it * 256;      // 0..1023
            int n = idx >> 4;              // 0..63
            int d4 = (idx & 15) * 4;
            size_t goff = kvbase + (size_t)(t0 + n) * D_ + d4;
            float4 kv = *(const float4*)(K + goff);
            float4 vv = *(const float4*)(V + goff);
            Kst[(d4 + 0) * KST_STRIDE + n] = kv.x;
            Kst[(d4 + 1) * KST_STRIDE + n] = kv.y;
            Kst[(d4 + 2) * KST_STRIDE + n] = kv.z;
            Kst[(d4 + 3) * KST_STRIDE + n] = kv.w;
            *(float4*)&Vs[n * KST_STRIDE + d4] = vv;
        }
        __syncthreads();

        // ---- scores GEMM: acc[i][j] = sum_d Qst[d][tm*8+i] * Kst[d][tn*4+j]
        float acc[8][4];
        #pragma unroll
        for (int i = 0; i < 8; i++)
            #pragma unroll
            for (int j = 0; j < 4; j++) acc[i][j] = 0.0f;

        #pragma unroll 8
        for (int d = 0; d < DH_; d++) {
            float av[8], bv[4];
            *(float4*)&av[0] = *(const float4*)&Qst[d * QST_STRIDE + tm * 8];
            *(float4*)&av[4] = *(const float4*)&Qst[d * QST_STRIDE + tm * 8 + 4];
            *(float4*)&bv[0] = *(const float4*)&Kst[d * KST_STRIDE + tn * 4];
            #pragma unroll
            for (int i = 0; i < 8; i++)
                #pragma unroll
                for (int j = 0; j < 4; j++)
                    acc[i][j] = fmaf(av[i], bv[j], acc[i][j]);
        }

        // ---- online softmax (log2 domain). tn spans lane bits 0..3.
        #pragma unroll
        for (int i = 0; i < 8; i++) {
            float rmax = fmaxf(fmaxf(acc[i][0], acc[i][1]),
                               fmaxf(acc[i][2], acc[i][3]));
            rmax = fmaxf(rmax, __shfl_xor_sync(0xffffffff, rmax, 1));
            rmax = fmaxf(rmax, __shfl_xor_sync(0xffffffff, rmax, 2));
            rmax = fmaxf(rmax, __shfl_xor_sync(0xffffffff, rmax, 4));
            rmax = fmaxf(rmax, __shfl_xor_sync(0xffffffff, rmax, 8));
            float mnew = fmaxf(m[i], rmax);
            float corr = exp2_fast(m[i] - mnew);
            m[i] = mnew;
            #pragma unroll
            for (int j = 0; j < 4; j++) {
                o[i][j] *= corr;
                acc[i][j] = exp2_fast(acc[i][j] - mnew);  // p
            }
            float rsum = (acc[i][0] + acc[i][1]) + (acc[i][2] + acc[i][3]);
            rsum += __shfl_xor_sync(0xffffffff, rsum, 1);
            rsum += __shfl_xor_sync(0xffffffff, rsum, 2);
            rsum += __shfl_xor_sync(0xffffffff, rsum, 4);
            rsum += __shfl_xor_sync(0xffffffff, rsum, 8);
            l[i] = l[i] * corr + rsum;
        }

        // ---- write P transposed: Pst[n][m], n = tn*4+j, m = tm*8+i
        #pragma unroll
        for (int j = 0; j < 4; j++) {
            float4 p0, p1;
            p0.x = acc[0][j]; p0.y = acc[1][j]; p0.z = acc[2][j]; p0.w = acc[3][j];
            p1.x = acc[4][j]; p1.y = acc[5][j]; p1.z = acc[6][j]; p1.w = acc[7][j];
            *(float4*)&Pst[(tn * 4 + j) * QST_STRIDE + tm * 8]     = p0;
            *(float4*)&Pst[(tn * 4 + j) * QST_STRIDE + tm * 8 + 4] = p1;
        }
        __syncthreads();

        // ---- PV GEMM: o[i][j] += sum_n Pst[n][tm*8+i] * Vs[n][tn*4+j]
        #pragma unroll 8
        for (int n = 0; n < AT_BN; n++) {
            float av[8], bv[4];
            *(float4*)&av[0] = *(const float4*)&Pst[n * QST_STRIDE + tm * 8];
            *(float4*)&av[4] = *(const float4*)&Pst[n * QST_STRIDE + tm * 8 + 4];
            *(float4*)&bv[0] = *(const float4*)&Vs[n * KST_STRIDE + tn * 4];
            #pragma unroll
            for (int i = 0; i < 8; i++)
                #pragma unroll
                for (int j = 0; j < 4; j++)
                    o[i][j] = fmaf(av[i], bv[j], o[i][j]);
        }
    }

    // ---- epilogue: normalize and store
    #pragma unroll
    for (int i = 0; i < 8; i++) {
        const int row = qblk * AT_BM + tm * 8 + i;
        const float inv = 1.0f / l[i];
        float4 ov;
        ov.x = o[i][0] * inv;
        ov.y = o[i][1] * inv;
        ov.z = o[i][2] * inv;
        ov.w = o[i][3] * inv;
        *(float4*)(O + ((size_t)b * S_ + row) * D_ + h * DH_ + tn * 4) = ov;
    }
}

// ---------------- launch ----------------
extern "C" void kernel_launch(void* const* d_in, const int* in_sizes, int n_in,
                              void* d_out, int out_size)
{
    const float* x  = (const float*)d_in[0];
    const float* Wq = (const float*)d_in[1];
    const float* bq = (const float*)d_in[2];
    const float* Wk = (const float*)d_in[3];
    const float* bk = (const float*)d_in[4];
    const float* Wv = (const float*)d_in[5];
    const float* bv = (const float*)d_in[6];
    const float* Wo = (const float*)d_in[7];
    const float* bo = (const float*)d_in[8];
    float* out = (float*)d_out;

    float *Qb, *Kb, *Vb, *Ob;
    cudaGetSymbolAddress((void**)&Qb, g_q);
    cudaGetSymbolAddress((void**)&Kb, g_k);
    cudaGetSymbolAddress((void**)&Vb, g_v);
    cudaGetSymbolAddress((void**)&Ob, g_o);

    const int M = B_ * S_;   // 8192
    const int N = D_;        // 512

    dim3 qkv_grid(N / GN, M / GM, 3);   // (4, 64, 3) = 768 blocks
    gemm_qkv<<<qkv_grid, 256>>>(x, Wq, bq, Qb, Wk, bk, Kb, Wv, bv, Vb);

    const int attn_smem = ATTN_SMEM_FLOATS * (int)sizeof(float);  // 102400 B
    cudaFuncSetAttribute(attn_kernel, cudaFuncAttributeMaxDynamicSharedMemorySize,
                         attn_smem);
    dim3 agrid(S_ / AT_BM, H_, B_);  // (32, 8, 2) = 512 blocks
    attn_kernel<<<agrid, 256, attn_smem>>>(Qb, Kb, Vb, Ob);

    dim3 ggrid(N / GN, M / GM);   // (4, 64)
    gemm_single<<<ggrid, 256>>>(Ob, Wo, bo, out);
}

// round 4
// speedup vs baseline: 3.1817x; 2.3596x over previous
#include <cuda_runtime.h>
#include <cstddef>
#include <cstdint>

// Problem constants
#define B_ 2
#define S_ 4096
#define D_ 512
#define H_ 8
#define DH_ 64

// ---------------- scratch (no allocation allowed) ----------------
__device__ __align__(16) float g_q[(size_t)B_ * S_ * D_];
__device__ __align__(16) float g_k[(size_t)B_ * S_ * D_];
__device__ __align__(16) float g_v[(size_t)B_ * S_ * D_];
__device__ __align__(16) float g_o[(size_t)B_ * S_ * D_];

// ---------------- helpers ----------------
__device__ __forceinline__ uint32_t f2tf(float x) {  // fp32 -> tf32 bits (rna)
    uint32_t r;
    asm("cvt.rna.tf32.f32 %0, %1;" : "=r"(r) : "f"(x));
    return r;
}
__device__ __forceinline__ float f2tff(float x) { return __uint_as_float(f2tf(x)); }

// warp-level tf32 MMA: D(16x8) += A(16x8) * B(8x8), fp32 accum
__device__ __forceinline__ void mma8(float* d, const uint32_t* a,
                                     uint32_t b0, uint32_t b1) {
    asm volatile(
        "mma.sync.aligned.m16n8k8.row.col.f32.tf32.tf32.f32 "
        "{%0,%1,%2,%3}, {%4,%5,%6,%7}, {%8,%9}, {%0,%1,%2,%3};"
        : "+f"(d[0]), "+f"(d[1]), "+f"(d[2]), "+f"(d[3])
        : "r"(a[0]), "r"(a[1]), "r"(a[2]), "r"(a[3]), "r"(b0), "r"(b1));
}

__device__ __forceinline__ float exp2_fast(float x) {
    x = fmaxf(x, -120.0f);
    float r = rintf(x);
    float f = x - r;
    float p = 1.3333558e-3f;
    p = fmaf(p, f, 9.6181291e-3f);
    p = fmaf(p, f, 5.5504109e-2f);
    p = fmaf(p, f, 2.4022651e-1f);
    p = fmaf(p, f, 6.9314718e-1f);
    p = fmaf(p, f, 1.0f);
    int i = (int)r;
    return __int_as_float(__float_as_int(p) + (i << 23));
}

// ================= projection GEMM: C = relu(A[M,512] @ W[512,512] + b) =====
// Block 128x128, k-tile 32. 8 warps as 2(m) x 4(n); warp tile 64m x 32n.
#define AS_STR 36
#define WS_STR 136

__device__ __forceinline__ void gemm_mma_body(
    const float* __restrict__ A, const float* __restrict__ W,
    const float* __restrict__ bias, float* __restrict__ C,
    int bm, int bn)
{
    __shared__ float As[128 * AS_STR];  // A tile [128 m][32 k]
    __shared__ float Ws[32 * WS_STR];   // W tile [32 k][128 n]

    const int tid = threadIdx.x;
    const int lane = tid & 31;
    const int wid = tid >> 5;
    const int wm = wid >> 2;        // 0..1
    const int wn = wid & 3;         // 0..3
    const int g = lane >> 2;        // 0..7
    const int c = lane & 3;         // 0..3

    // staging maps
    const int arow = tid >> 1;            // 0..127
    const int akq = (tid & 1) * 16;       // 0 or 16 (float index), 4 f4/thread? no:
    // A tile = 128x32 = 4096 floats = 1024 float4; 256 threads -> 4 each
    // mapping: idx = tid + i*256 : arow_i = idx>>3, akq_i = (idx&7)*4
    // W tile = 32x128 = 4096 floats = 1024 float4; wrow = idx>>5, wnq = (idx&31)*4
    (void)arow; (void)akq;

    float acc[4][4][4];
    #pragma unroll
    for (int mt = 0; mt < 4; mt++)
        #pragma unroll
        for (int nt = 0; nt < 4; nt++)
            #pragma unroll
            for (int j = 0; j < 4; j++) acc[mt][nt][j] = 0.0f;

    float4 pa[4], pw[4];
    #pragma unroll
    for (int i = 0; i < 4; i++) {
        int idx = tid + i * 256;
        pa[i] = *(const float4*)(A + (size_t)(bm + (idx >> 3)) * D_ + (idx & 7) * 4);
        pw[i] = *(const float4*)(W + (size_t)(idx >> 5) * D_ + bn + (idx & 31) * 4);
    }

    for (int kt = 0; kt < 16; kt++) {
        __syncthreads();
        #pragma unroll
        for (int i = 0; i < 4; i++) {
            int idx = tid + i * 256;
            float4 a = pa[i], w = pw[i];
            a.x = f2tff(a.x); a.y = f2tff(a.y); a.z = f2tff(a.z); a.w = f2tff(a.w);
            w.x = f2tff(w.x); w.y = f2tff(w.y); w.z = f2tff(w.z); w.w = f2tff(w.w);
            *(float4*)&As[(idx >> 3) * AS_STR + (idx & 7) * 4] = a;
            *(float4*)&Ws[(idx >> 5) * WS_STR + (idx & 31) * 4] = w;
        }
        __syncthreads();

        if (kt < 15) {
            #pragma unroll
            for (int i = 0; i < 4; i++) {
                int idx = tid + i * 256;
                pa[i] = *(const float4*)(A + (size_t)(bm + (idx >> 3)) * D_ +
                                         (kt + 1) * 32 + (idx & 7) * 4);
                pw[i] = *(const float4*)(W + (size_t)((kt + 1) * 32 + (idx >> 5)) * D_ +
                                         bn + (idx & 31) * 4);
            }
        }

        #pragma unroll
        for (int ks = 0; ks < 4; ks++) {
            uint32_t af[4][4];
            #pragma unroll
            for (int mt = 0; mt < 4; mt++) {
                int mrow = wm * 64 + mt * 16 + g;
                int kk = ks * 8 + c;
                af[mt][0] = __float_as_uint(As[mrow * AS_STR + kk]);
                af[mt][1] = __float_as_uint(As[(mrow + 8) * AS_STR + kk]);
                af[mt][2] = __float_as_uint(As[mrow * AS_STR + kk + 4]);
                af[mt][3] = __float_as_uint(As[(mrow + 8) * AS_STR + kk + 4]);
            }
            #pragma unroll
            for (int nt = 0; nt < 4; nt++) {
                int ncol = wn * 32 + nt * 8 + g;
                int kk = ks * 8 + c;
                uint32_t b0 = __float_as_uint(Ws[kk * WS_STR + ncol]);
                uint32_t b1 = __float_as_uint(Ws[(kk + 4) * WS_STR + ncol]);
                #pragma unroll
                for (int mt = 0; mt < 4; mt++)
                    mma8(acc[mt][nt], af[mt], b0, b1);
            }
        }
    }

    // epilogue: bias + relu, store pairs
    #pragma unroll
    for (int mt = 0; mt < 4; mt++) {
        const int row = bm + wm * 64 + mt * 16 + g;
        #pragma unroll
        for (int nt = 0; nt < 4; nt++) {
            const int col = bn + wn * 32 + nt * 8 + 2 * c;
            const float b0 = bias[col], b1 = bias[col + 1];
            float2 v0, v1;
            v0.x = fmaxf(acc[mt][nt][0] + b0, 0.0f);
            v0.y = fmaxf(acc[mt][nt][1] + b1, 0.0f);
            v1.x = fmaxf(acc[mt][nt][2] + b0, 0.0f);
            v1.y = fmaxf(acc[mt][nt][3] + b1, 0.0f);
            *(float2*)(C + (size_t)row * D_ + col) = v0;
            *(float2*)(C + (size_t)(row + 8) * D_ + col) = v1;
        }
    }
}

__global__ void __launch_bounds__(256)
gemm_mma_qkv(const float* __restrict__ x,
             const float* __restrict__ Wq, const float* __restrict__ bq, float* __restrict__ Q,
             const float* __restrict__ Wk, const float* __restrict__ bk, float* __restrict__ K,
             const float* __restrict__ Wv, const float* __restrict__ bv, float* __restrict__ V)
{
    const float* W; const float* bias; float* C;
    if (blockIdx.z == 0)      { W = Wq; bias = bq; C = Q; }
    else if (blockIdx.z == 1) { W = Wk; bias = bk; C = K; }
    else                      { W = Wv; bias = bv; C = V; }
    gemm_mma_body(x, W, bias, C, blockIdx.y * 128, blockIdx.x * 128);
}

__global__ void __launch_bounds__(256)
gemm_mma_one(const float* __restrict__ A, const float* __restrict__ W,
             const float* __restrict__ bias, float* __restrict__ C)
{
    gemm_mma_body(A, W, bias, C, blockIdx.y * 128, blockIdx.x * 128);
}

// ================= flash attention with tf32 mma =================
// BM=128 q rows, BN=64 keys/tile, 256 threads (8 warps x 16m x 64n warp tiles).
#define PS_STR 68
#define KV_STR 72
// Ps[128][68] (also Q staging), Kts[64][72], Vs[64][72]
#define ATTN_SMEM_FLOATS (128 * PS_STR + 2 * 64 * KV_STR)

__global__ void __launch_bounds__(256)
attn_mma(const float* __restrict__ Q, const float* __restrict__ K,
         const float* __restrict__ V, float* __restrict__ O)
{
    extern __shared__ float sm[];
    float* Ps  = sm;                         // [128][PS_STR]  m x key (and Q staging m x d)
    float* Kts = sm + 128 * PS_STR;          // [64][KV_STR]   d x key (swizzled cols)
    float* Vs  = Kts + 64 * KV_STR;          // [64][KV_STR]   key x d

    const int tid = threadIdx.x;
    const int lane = tid & 31;
    const int wid = tid >> 5;
    const int g = lane >> 2;   // 0..7
    const int c = lane & 3;    // 0..3
    const int qblk = blockIdx.x;
    const int h = blockIdx.y;
    const int b = blockIdx.z;

    const float scale = 0.125f * 1.44269504f;  // 1/sqrt(64) * log2(e)

    // ---- prologue: stage Q (scaled, tf32) into Ps[m][d]
    {
        const float* qbase = Q + ((size_t)b * S_ + qblk * 128) * D_ + h * DH_;
        #pragma unroll
        for (int it = 0; it < 8; it++) {
            int idx = tid + it * 256;
            int mrow = idx >> 4;
            int d4 = (idx & 15) * 4;
            float4 t = *(const float4*)(qbase + (size_t)mrow * D_ + d4);
            t.x = f2tff(t.x * scale); t.y = f2tff(t.y * scale);
            t.z = f2tff(t.z * scale); t.w = f2tff(t.w * scale);
            *(float4*)&Ps[mrow * PS_STR + d4] = t;
        }
    }
    __syncthreads();

    // Q fragments to registers (reused every tile)
    const int prow0 = (wid * 16 + g) * PS_STR;
    const int prow1 = prow0 + 8 * PS_STR;
    uint32_t qf[8][4];
    #pragma unroll
    for (int ks = 0; ks < 8; ks++) {
        int kk = ks * 8 + c;
        qf[ks][0] = __float_as_uint(Ps[prow0 + kk]);
        qf[ks][1] = __float_as_uint(Ps[prow1 + kk]);
        qf[ks][2] = __float_as_uint(Ps[prow0 + kk + 4]);
        qf[ks][3] = __float_as_uint(Ps[prow1 + kk + 4]);
    }

    float o[8][4];
    #pragma unroll
    for (int nt = 0; nt < 8; nt++)
        #pragma unroll
        for (int j = 0; j < 4; j++) o[nt][j] = 0.0f;
    float m0 = -1e30f, m1 = -1e30f, l0 = 0.0f, l1 = 0.0f;

    const size_t kvbase = (size_t)b * S_ * D_ + h * DH_;

    for (int t0 = 0; t0 < S_; t0 += 64) {
        __syncthreads();  // all prior frag reads done (also covers prologue)

        // ---- stage K transposed (swizzled) + V natural, tf32
        #pragma unroll
        for (int it = 0; it < 4; it++) {
            int idx = tid + it * 256;
            int n = idx >> 4;              // key 0..63
            int d4 = (idx & 15) * 4;
            size_t goff = kvbase + (size_t)(t0 + n) * D_ + d4;
            float4 kv = *(const float4*)(K + goff);
            float4 vv = *(const float4*)(V + goff);
            int swz = ((d4 >> 2) & 15) * 2;      // uniform over the 4 d's
            int nsw = n ^ swz;
            Kts[(d4 + 0) * KV_STR + nsw] = f2tff(kv.x);
            Kts[(d4 + 1) * KV_STR + nsw] = f2tff(kv.y);
            Kts[(d4 + 2) * KV_STR + nsw] = f2tff(kv.z);
            Kts[(d4 + 3) * KV_STR + nsw] = f2tff(kv.w);
            vv.x = f2tff(vv.x); vv.y = f2tff(vv.y);
            vv.z = f2tff(vv.z); vv.w = f2tff(vv.w);
            *(float4*)&Vs[n * KV_STR + d4] = vv;
        }
        __syncthreads();

        // ---- S = Q @ K^T  (warp: 16 rows x 64 keys)
        float sacc[8][4];
        #pragma unroll
        for (int nt = 0; nt < 8; nt++)
            #pragma unroll
            for (int j = 0; j < 4; j++) sacc[nt][j] = 0.0f;

        #pragma unroll
        for (int ks = 0; ks < 8; ks++) {
            int k0 = ks * 8 + c;
            int swz0 = ((k0 >> 2) & 15) * 2;
            int swz1 = (((k0 + 4) >> 2) & 15) * 2;
            #pragma unroll
            for (int nt = 0; nt < 8; nt++) {
                int col = nt * 8 + g;
                uint32_t b0 = __float_as_uint(Kts[k0 * KV_STR + (col ^ swz0)]);
                uint32_t b1 = __float_as_uint(Kts[(k0 + 4) * KV_STR + (col ^ swz1)]);
                mma8(sacc[nt], qf[ks], b0, b1);
            }
        }

        // ---- online softmax (log2 domain); thread owns rows g and g+8
        float tm0 = -1e30f, tm1 = -1e30f;
        #pragma unroll
        for (int nt = 0; nt < 8; nt++) {
            tm0 = fmaxf(tm0, fmaxf(sacc[nt][0], sacc[nt][1]));
            tm1 = fmaxf(tm1, fmaxf(sacc[nt][2], sacc[nt][3]));
        }
        tm0 = fmaxf(tm0, __shfl_xor_sync(0xffffffff, tm0, 1));
        tm0 = fmaxf(tm0, __shfl_xor_sync(0xffffffff, tm0, 2));
        tm1 = fmaxf(tm1, __shfl_xor_sync(0xffffffff, tm1, 1));
        tm1 = fmaxf(tm1, __shfl_xor_sync(0xffffffff, tm1, 2));

        float mn0 = fmaxf(m0, tm0), mn1 = fmaxf(m1, tm1);
        float corr0 = exp2_fast(m0 - mn0), corr1 = exp2_fast(m1 - mn1);
        m0 = mn0; m1 = mn1;

        float rs0 = 0.0f, rs1 = 0.0f;
        #pragma unroll
        for (int nt = 0; nt < 8; nt++) {
            sacc[nt][0] = exp2_fast(sacc[nt][0] - m0);
            sacc[nt][1] = exp2_fast(sacc[nt][1] - m0);
            sacc[nt][2] = exp2_fast(sacc[nt][2] - m1);
            sacc[nt][3] = exp2_fast(sacc[nt][3] - m1);
            rs0 += sacc[nt][0] + sacc[nt][1];
            rs1 += sacc[nt][2] + sacc[nt][3];
        }
        rs0 += __shfl_xor_sync(0xffffffff, rs0, 1);
        rs0 += __shfl_xor_sync(0xffffffff, rs0, 2);
        rs1 += __shfl_xor_sync(0xffffffff, rs1, 1);
        rs1 += __shfl_xor_sync(0xffffffff, rs1, 2);
        l0 = l0 * corr0 + rs0;
        l1 = l1 * corr1 + rs1;
        #pragma unroll
        for (int nt = 0; nt < 8; nt++) {
            o[nt][0] *= corr0; o[nt][1] *= corr0;
            o[nt][2] *= corr1; o[nt][3] *= corr1;
        }

        // ---- store P fragments (tf32) into Ps[m][key]; warp-private rows
        #pragma unroll
        for (int nt = 0; nt < 8; nt++) {
            float2 p01, p23;
            p01.x = f2tff(sacc[nt][0]); p01.y = f2tff(sacc[nt][1]);
            p23.x = f2tff(sacc[nt][2]); p23.y = f2tff(sacc[nt][3]);
            *(float2*)&Ps[prow0 + nt * 8 + 2 * c] = p01;
            *(float2*)&Ps[prow1 + nt * 8 + 2 * c] = p23;
        }
        __syncwarp();

        // ---- O += P @ V  (A from Ps, B from Vs)
        #pragma unroll
        for (int ks = 0; ks < 8; ks++) {
            int kk = ks * 8 + c;
            uint32_t af[4];
            af[0] = __float_as_uint(Ps[prow0 + kk]);
            af[1] = __float_as_uint(Ps[prow1 + kk]);
            af[2] = __float_as_uint(Ps[prow0 + kk + 4]);
            af[3] = __float_as_uint(Ps[prow1 + kk + 4]);
            #pragma unroll
            for (int nt = 0; nt < 8; nt++) {
                int col = nt * 8 + g;
                uint32_t b0 = __float_as_uint(Vs[kk * KV_STR + col]);
                uint32_t b1 = __float_as_uint(Vs[(kk + 4) * KV_STR + col]);
                mma8(o[nt], af, b0, b1);
            }
        }
    }

    // ---- epilogue
    const float inv0 = 1.0f / l0, inv1 = 1.0f / l1;
    float* obase = O + ((size_t)b * S_ + qblk * 128 + wid * 16 + g) * D_ + h * DH_;
    #pragma unroll
    for (int nt = 0; nt < 8; nt++) {
        float2 v0, v1;
        v0.x = o[nt][0] * inv0; v0.y = o[nt][1] * inv0;
        v1.x = o[nt][2] * inv1; v1.y = o[nt][3] * inv1;
        *(float2*)(obase + nt * 8 + 2 * c) = v0;
        *(float2*)(obase + (size_t)8 * D_ + nt * 8 + 2 * c) = v1;
    }
}

// ---------------- launch ----------------
extern "C" void kernel_launch(void* const* d_in, const int* in_sizes, int n_in,
                              void* d_out, int out_size)
{
    const float* x  = (const float*)d_in[0];
    const float* Wq = (const float*)d_in[1];
    const float* bq = (const float*)d_in[2];
    const float* Wk = (const float*)d_in[3];
    const float* bk = (const float*)d_in[4];
    const float* Wv = (const float*)d_in[5];
    const float* bv = (const float*)d_in[6];
    const float* Wo = (const float*)d_in[7];
    const float* bo = (const float*)d_in[8];
    float* out = (float*)d_out;

    float *Qb, *Kb, *Vb, *Ob;
    cudaGetSymbolAddress((void**)&Qb, g_q);
    cudaGetSymbolAddress((void**)&Kb, g_k);
    cudaGetSymbolAddress((void**)&Vb, g_v);
    cudaGetSymbolAddress((void**)&Ob, g_o);

    dim3 qkv_grid(D_ / 128, (B_ * S_) / 128, 3);   // (4, 64, 3)
    gemm_mma_qkv<<<qkv_grid, 256>>>(x, Wq, bq, Qb, Wk, bk, Kb, Wv, bv, Vb);

    const int attn_smem = ATTN_SMEM_FLOATS * (int)sizeof(float);  // 71680 B
    cudaFuncSetAttribute(attn_mma, cudaFuncAttributeMaxDynamicSharedMemorySize,
                         attn_smem);
    dim3 agrid(S_ / 128, H_, B_);  // (32, 8, 2)
    attn_mma<<<agrid, 256, attn_smem>>>(Qb, Kb, Vb, Ob);

    dim3 ogrid(D_ / 128, (B_ * S_) / 128);         // (4, 64)
    gemm_mma_one<<<ogrid, 256>>>(Ob, Wo, bo, out);
}

// round 5
// speedup vs baseline: 3.9920x; 1.2547x over previous
#include <cuda_runtime.h>
#include <cstddef>
#include <cstdint>

// Problem constants
#define B_ 2
#define S_ 4096
#define D_ 512
#define H_ 8
#define DH_ 64

// ---------------- scratch (no allocation allowed) ----------------
__device__ __align__(16) float g_q[(size_t)B_ * S_ * D_];
__device__ __align__(16) float g_k[(size_t)B_ * S_ * D_];
__device__ __align__(16) float g_v[(size_t)B_ * S_ * D_];
__device__ __align__(16) float g_o[(size_t)B_ * S_ * D_];

// ---------------- helpers ----------------
__device__ __forceinline__ uint32_t f2tf(float x) {  // fp32 -> tf32 bits (rna)
    uint32_t r;
    asm("cvt.rna.tf32.f32 %0, %1;" : "=r"(r) : "f"(x));
    return r;
}
__device__ __forceinline__ float f2tff(float x) { return __uint_as_float(f2tf(x)); }

// warp-level tf32 MMA: D(16x8) += A(16x8) * B(8x8), fp32 accum
__device__ __forceinline__ void mma8(float* d, const uint32_t* a,
                                     uint32_t b0, uint32_t b1) {
    asm volatile(
        "mma.sync.aligned.m16n8k8.row.col.f32.tf32.tf32.f32 "
        "{%0,%1,%2,%3}, {%4,%5,%6,%7}, {%8,%9}, {%0,%1,%2,%3};"
        : "+f"(d[0]), "+f"(d[1]), "+f"(d[2]), "+f"(d[3])
        : "r"(a[0]), "r"(a[1]), "r"(a[2]), "r"(a[3]), "r"(b0), "r"(b1));
}

// exp2 via magic-constant rounding + degree-4 poly. No F2I/F2F. err ~4e-5.
__device__ __forceinline__ float exp2_fast(float x) {
    x = fmaxf(x, -126.0f);
    float y = x + 12582912.0f;              // 1.5*2^23: RN-to-int in mantissa
    int n = __float_as_int(y);              // low bits hold round(x) (biased)
    float t = y - 12582912.0f;
    float f = x - t;                        // frac in [-0.5, 0.5]
    float p = fmaf(9.61813e-3f, f, 5.550411e-2f);
    p = fmaf(p, f, 2.4022651e-1f);
    p = fmaf(p, f, 6.9314718e-1f);
    p = fmaf(p, f, 1.0f);
    // (n<<23): bias bits of the magic constant shift out (low 9 bits are 0)
    return __int_as_float(__float_as_int(p) + (n << 23));
}

// ================= projection GEMM: C = relu(A[M,512] @ W[512,512] + b) =====
// Block 128x128, k-tile 32. 8 warps as 2(m) x 4(n); warp tile 64m x 32n.
#define AS_STR 36
#define WS_STR 136

__device__ __forceinline__ void gemm_mma_body(
    const float* __restrict__ A, const float* __restrict__ W,
    const float* __restrict__ bias, float* __restrict__ C,
    int bm, int bn)
{
    __shared__ float As[128 * AS_STR];  // A tile [128 m][32 k]
    __shared__ float Ws[32 * WS_STR];   // W tile [32 k][128 n]

    const int tid = threadIdx.x;
    const int lane = tid & 31;
    const int wid = tid >> 5;
    const int wm = wid >> 2;        // 0..1
    const int wn = wid & 3;         // 0..3
    const int g = lane >> 2;        // 0..7
    const int c = lane & 3;         // 0..3

    float acc[4][4][4];
    #pragma unroll
    for (int mt = 0; mt < 4; mt++)
        #pragma unroll
        for (int nt = 0; nt < 4; nt++)
            #pragma unroll
            for (int j = 0; j < 4; j++) acc[mt][nt][j] = 0.0f;

    float4 pa[4], pw[4];
    #pragma unroll
    for (int i = 0; i < 4; i++) {
        int idx = tid + i * 256;
        pa[i] = *(const float4*)(A + (size_t)(bm + (idx >> 3)) * D_ + (idx & 7) * 4);
        pw[i] = *(const float4*)(W + (size_t)(idx >> 5) * D_ + bn + (idx & 31) * 4);
    }

    for (int kt = 0; kt < 16; kt++) {
        __syncthreads();
        #pragma unroll
        for (int i = 0; i < 4; i++) {
            int idx = tid + i * 256;
            float4 a = pa[i], w = pw[i];
            a.x = f2tff(a.x); a.y = f2tff(a.y); a.z = f2tff(a.z); a.w = f2tff(a.w);
            w.x = f2tff(w.x); w.y = f2tff(w.y); w.z = f2tff(w.z); w.w = f2tff(w.w);
            *(float4*)&As[(idx >> 3) * AS_STR + (idx & 7) * 4] = a;
            *(float4*)&Ws[(idx >> 5) * WS_STR + (idx & 31) * 4] = w;
        }
        __syncthreads();

        if (kt < 15) {
            #pragma unroll
            for (int i = 0; i < 4; i++) {
                int idx = tid + i * 256;
                pa[i] = *(const float4*)(A + (size_t)(bm + (idx >> 3)) * D_ +
                                         (kt + 1) * 32 + (idx & 7) * 4);
                pw[i] = *(const float4*)(W + (size_t)((kt + 1) * 32 + (idx >> 5)) * D_ +
                                         bn + (idx & 31) * 4);
            }
        }

        #pragma unroll
        for (int ks = 0; ks < 4; ks++) {
            uint32_t af[4][4];
            #pragma unroll
            for (int mt = 0; mt < 4; mt++) {
                int mrow = wm * 64 + mt * 16 + g;
                int kk = ks * 8 + c;
                af[mt][0] = __float_as_uint(As[mrow * AS_STR + kk]);
                af[mt][1] = __float_as_uint(As[(mrow + 8) * AS_STR + kk]);
                af[mt][2] = __float_as_uint(As[mrow * AS_STR + kk + 4]);
                af[mt][3] = __float_as_uint(As[(mrow + 8) * AS_STR + kk + 4]);
            }
            #pragma unroll
            for (int nt = 0; nt < 4; nt++) {
                int ncol = wn * 32 + nt * 8 + g;
                int kk = ks * 8 + c;
                uint32_t b0 = __float_as_uint(Ws[kk * WS_STR + ncol]);
                uint32_t b1 = __float_as_uint(Ws[(kk + 4) * WS_STR + ncol]);
                #pragma unroll
                for (int mt = 0; mt < 4; mt++)
                    mma8(acc[mt][nt], af[mt], b0, b1);
            }
        }
    }

    #pragma unroll
    for (int mt = 0; mt < 4; mt++) {
        const int row = bm + wm * 64 + mt * 16 + g;
        #pragma unroll
        for (int nt = 0; nt < 4; nt++) {
            const int col = bn + wn * 32 + nt * 8 + 2 * c;
            const float b0 = bias[col], b1 = bias[col + 1];
            float2 v0, v1;
            v0.x = fmaxf(acc[mt][nt][0] + b0, 0.0f);
            v0.y = fmaxf(acc[mt][nt][1] + b1, 0.0f);
            v1.x = fmaxf(acc[mt][nt][2] + b0, 0.0f);
            v1.y = fmaxf(acc[mt][nt][3] + b1, 0.0f);
            *(float2*)(C + (size_t)row * D_ + col) = v0;
            *(float2*)(C + (size_t)(row + 8) * D_ + col) = v1;
        }
    }
}

__global__ void __launch_bounds__(256)
gemm_mma_qkv(const float* __restrict__ x,
             const float* __restrict__ Wq, const float* __restrict__ bq, float* __restrict__ Q,
             const float* __restrict__ Wk, const float* __restrict__ bk, float* __restrict__ K,
             const float* __restrict__ Wv, const float* __restrict__ bv, float* __restrict__ V)
{
    const float* W; const float* bias; float* C;
    if (blockIdx.z == 0)      { W = Wq; bias = bq; C = Q; }
    else if (blockIdx.z == 1) { W = Wk; bias = bk; C = K; }
    else                      { W = Wv; bias = bv; C = V; }
    gemm_mma_body(x, W, bias, C, blockIdx.y * 128, blockIdx.x * 128);
}

__global__ void __launch_bounds__(256)
gemm_mma_one(const float* __restrict__ A, const float* __restrict__ W,
             const float* __restrict__ bias, float* __restrict__ C)
{
    gemm_mma_body(A, W, bias, C, blockIdx.y * 128, blockIdx.x * 128);
}

// ================= flash attention with tf32 mma =================
// BM=64 q rows, BN=64 keys/tile, 128 threads (4 warps x 16m x 64n warp tiles).
// Small block -> 3 blocks/SM (occupancy), per-warp work unchanged.
#define AT_BM 64
#define PS_STR 68
#define KV_STR 72
// Ps[64][68] (also Q staging), Kts[64][72], Vs[64][72]
#define ATTN_SMEM_FLOATS (AT_BM * PS_STR + 2 * 64 * KV_STR)

__global__ void __launch_bounds__(128)
attn_mma(const float* __restrict__ Q, const float* __restrict__ K,
         const float* __restrict__ V, float* __restrict__ O)
{
    extern __shared__ float sm[];
    float* Ps  = sm;                         // [64][PS_STR]  m x key (and Q staging)
    float* Kts = sm + AT_BM * PS_STR;        // [64][KV_STR]  d x key (swizzled cols)
    float* Vs  = Kts + 64 * KV_STR;          // [64][KV_STR]  key x d

    const int tid = threadIdx.x;
    const int lane = tid & 31;
    const int wid = tid >> 5;
    const int g = lane >> 2;   // 0..7
    const int c = lane & 3;    // 0..3
    const int qblk = blockIdx.x;
    const int h = blockIdx.y;
    const int b = blockIdx.z;

    const float scale = 0.125f * 1.44269504f;  // 1/sqrt(64) * log2(e)

    // ---- prologue: stage Q (scaled, tf32) into Ps[m][d]
    {
        const float* qbase = Q + ((size_t)b * S_ + qblk * AT_BM) * D_ + h * DH_;
        #pragma unroll 4
        for (int it = 0; it < 8; it++) {
            int idx = tid + it * 128;        // 0..1023
            int mrow = idx >> 4;             // 0..63
            int d4 = (idx & 15) * 4;
            float4 t = *(const float4*)(qbase + (size_t)mrow * D_ + d4);
            t.x = f2tff(t.x * scale); t.y = f2tff(t.y * scale);
            t.z = f2tff(t.z * scale); t.w = f2tff(t.w * scale);
            *(float4*)&Ps[mrow * PS_STR + d4] = t;
        }
    }
    __syncthreads();

    // Q fragments to registers (reused every tile)
    const int prow0 = (wid * 16 + g) * PS_STR;
    const int prow1 = prow0 + 8 * PS_STR;
    uint32_t qf[8][4];
    #pragma unroll
    for (int ks = 0; ks < 8; ks++) {
        int kk = ks * 8 + c;
        qf[ks][0] = __float_as_uint(Ps[prow0 + kk]);
        qf[ks][1] = __float_as_uint(Ps[prow1 + kk]);
        qf[ks][2] = __float_as_uint(Ps[prow0 + kk + 4]);
        qf[ks][3] = __float_as_uint(Ps[prow1 + kk + 4]);
    }

    float o[8][4];
    #pragma unroll
    for (int nt = 0; nt < 8; nt++)
        #pragma unroll
        for (int j = 0; j < 4; j++) o[nt][j] = 0.0f;
    float m0 = -1e30f, m1 = -1e30f, l0 = 0.0f, l1 = 0.0f;

    const size_t kvbase = (size_t)b * S_ * D_ + h * DH_;

    for (int t0 = 0; t0 < S_; t0 += 64) {
        __syncthreads();  // all prior frag reads done (also covers prologue)

        // ---- stage K transposed (swizzled) + V natural, tf32
        #pragma unroll 4
        for (int it = 0; it < 8; it++) {
            int idx = tid + it * 128;
            int n = idx >> 4;              // key 0..63
            int d4 = (idx & 15) * 4;
            size_t goff = kvbase + (size_t)(t0 + n) * D_ + d4;
            float4 kv = *(const float4*)(K + goff);
            float4 vv = *(const float4*)(V + goff);
            int swz = ((d4 >> 2) & 15) * 2;      // uniform over the 4 d's
            int nsw = n ^ swz;
            Kts[(d4 + 0) * KV_STR + nsw] = f2tff(kv.x);
            Kts[(d4 + 1) * KV_STR + nsw] = f2tff(kv.y);
            Kts[(d4 + 2) * KV_STR + nsw] = f2tff(kv.z);
            Kts[(d4 + 3) * KV_STR + nsw] = f2tff(kv.w);
            vv.x = f2tff(vv.x); vv.y = f2tff(vv.y);
            vv.z = f2tff(vv.z); vv.w = f2tff(vv.w);
            *(float4*)&Vs[n * KV_STR + d4] = vv;
        }
        __syncthreads();

        // ---- S = Q @ K^T  (warp: 16 rows x 64 keys)
        float sacc[8][4];
        #pragma unroll
        for (int nt = 0; nt < 8; nt++)
            #pragma unroll
            for (int j = 0; j < 4; j++) sacc[nt][j] = 0.0f;

        #pragma unroll
        for (int ks = 0; ks < 8; ks++) {
            int k0 = ks * 8 + c;
            int swz0 = ((k0 >> 2) & 15) * 2;
            int swz1 = (((k0 + 4) >> 2) & 15) * 2;
            #pragma unroll
            for (int nt = 0; nt < 8; nt++) {
                int col = nt * 8 + g;
                uint32_t b0 = __float_as_uint(Kts[k0 * KV_STR + (col ^ swz0)]);
                uint32_t b1 = __float_as_uint(Kts[(k0 + 4) * KV_STR + (col ^ swz1)]);
                mma8(sacc[nt], qf[ks], b0, b1);
            }
        }

        // ---- online softmax (log2 domain); thread owns rows g and g+8
        float tm0 = -1e30f, tm1 = -1e30f;
        #pragma unroll
        for (int nt = 0; nt < 8; nt++) {
            tm0 = fmaxf(tm0, fmaxf(sacc[nt][0], sacc[nt][1]));
            tm1 = fmaxf(tm1, fmaxf(sacc[nt][2], sacc[nt][3]));
        }
        tm0 = fmaxf(tm0, __shfl_xor_sync(0xffffffff, tm0, 1));
        tm0 = fmaxf(tm0, __shfl_xor_sync(0xffffffff, tm0, 2));
        tm1 = fmaxf(tm1, __shfl_xor_sync(0xffffffff, tm1, 1));
        tm1 = fmaxf(tm1, __shfl_xor_sync(0xffffffff, tm1, 2));

        float mn0 = fmaxf(m0, tm0), mn1 = fmaxf(m1, tm1);
        float corr0 = exp2_fast(m0 - mn0), corr1 = exp2_fast(m1 - mn1);
        m0 = mn0; m1 = mn1;

        float rs0 = 0.0f, rs1 = 0.0f;
        #pragma unroll
        for (int nt = 0; nt < 8; nt++) {
            sacc[nt][0] = exp2_fast(sacc[nt][0] - m0);
            sacc[nt][1] = exp2_fast(sacc[nt][1] - m0);
            sacc[nt][2] = exp2_fast(sacc[nt][2] - m1);
            sacc[nt][3] = exp2_fast(sacc[nt][3] - m1);
            rs0 += sacc[nt][0] + sacc[nt][1];
            rs1 += sacc[nt][2] + sacc[nt][3];
        }
        rs0 += __shfl_xor_sync(0xffffffff, rs0, 1);
        rs0 += __shfl_xor_sync(0xffffffff, rs0, 2);
        rs1 += __shfl_xor_sync(0xffffffff, rs1, 1);
        rs1 += __shfl_xor_sync(0xffffffff, rs1, 2);
        l0 = l0 * corr0 + rs0;
        l1 = l1 * corr1 + rs1;
        #pragma unroll
        for (int nt = 0; nt < 8; nt++) {
            o[nt][0] *= corr0; o[nt][1] *= corr0;
            o[nt][2] *= corr1; o[nt][3] *= corr1;
        }

        // ---- store P fragments into Ps[m][key]; warp-private rows.
        // (no tf32 cvt: MMA truncation adds ~1e-4 err, within budget)
        #pragma unroll
        for (int nt = 0; nt < 8; nt++) {
            float2 p01, p23;
            p01.x = sacc[nt][0]; p01.y = sacc[nt][1];
            p23.x = sacc[nt][2]; p23.y = sacc[nt][3];
            *(float2*)&Ps[prow0 + nt * 8 + 2 * c] = p01;
            *(float2*)&Ps[prow1 + nt * 8 + 2 * c] = p23;
        }
        __syncwarp();

        // ---- O += P @ V  (A from Ps, B from Vs)
        #pragma unroll
        for (int ks = 0; ks < 8; ks++) {
            int kk = ks * 8 + c;
            uint32_t af[4];
            af[0] = __float_as_uint(Ps[prow0 + kk]);
            af[1] = __float_as_uint(Ps[prow1 + kk]);
            af[2] = __float_as_uint(Ps[prow0 + kk + 4]);
            af[3] = __float_as_uint(Ps[prow1 + kk + 4]);
            #pragma unroll
            for (int nt = 0; nt < 8; nt++) {
                int col = nt * 8 + g;
                uint32_t b0 = __float_as_uint(Vs[kk * KV_STR + col]);
                uint32_t b1 = __float_as_uint(Vs[(kk + 4) * KV_STR + col]);
                mma8(o[nt], af, b0, b1);
            }
        }
    }

    // ---- epilogue
    const float inv0 = 1.0f / l0, inv1 = 1.0f / l1;
    float* obase = O + ((size_t)b * S_ + qblk * AT_BM + wid * 16 + g) * D_ + h * DH_;
    #pragma unroll
    for (int nt = 0; nt < 8; nt++) {
        float2 v0, v1;
        v0.x = o[nt][0] * inv0; v0.y = o[nt][1] * inv0;
        v1.x = o[nt][2] * inv1; v1.y = o[nt][3] * inv1;
        *(float2*)(obase + nt * 8 + 2 * c) = v0;
        *(float2*)(obase + (size_t)8 * D_ + nt * 8 + 2 * c) = v1;
    }
}

// ---------------- launch ----------------
extern "C" void kernel_launch(void* const* d_in, const int* in_sizes, int n_in,
                              void* d_out, int out_size)
{
    const float* x  = (const float*)d_in[0];
    const float* Wq = (const float*)d_in[1];
    const float* bq = (const float*)d_in[2];
    const float* Wk = (const float*)d_in[3];
    const float* bk = (const float*)d_in[4];
    const float* Wv = (const float*)d_in[5];
    const float* bv = (const float*)d_in[6];
    const float* Wo = (const float*)d_in[7];
    const float* bo = (const float*)d_in[8];
    float* out = (float*)d_out;

    float *Qb, *Kb, *Vb, *Ob;
    cudaGetSymbolAddress((void**)&Qb, g_q);
    cudaGetSymbolAddress((void**)&Kb, g_k);
    cudaGetSymbolAddress((void**)&Vb, g_v);
    cudaGetSymbolAddress((void**)&Ob, g_o);

    dim3 qkv_grid(D_ / 128, (B_ * S_) / 128, 3);   // (4, 64, 3)
    gemm_mma_qkv<<<qkv_grid, 256>>>(x, Wq, bq, Qb, Wk, bk, Kb, Wv, bv, Vb);

    const int attn_smem = ATTN_SMEM_FLOATS * (int)sizeof(float);  // 54272 B
    cudaFuncSetAttribute(attn_mma, cudaFuncAttributeMaxDynamicSharedMemorySize,
                         attn_smem);
    dim3 agrid(S_ / AT_BM, H_, B_);  // (64, 8, 2) = 1024 blocks
    attn_mma<<<agrid, 128, attn_smem>>>(Qb, Kb, Vb, Ob);

    dim3 ogrid(D_ / 128, (B_ * S_) / 128);         // (4, 64)
    gemm_mma_one<<<ogrid, 256>>>(Ob, Wo, bo, out);
}

// round 6
// speedup vs baseline: 3.9938x; 1.0004x over previous
#include <cuda_runtime.h>
#include <cstddef>
#include <cstdint>

// Problem constants
#define B_ 2
#define S_ 4096
#define D_ 512
#define H_ 8
#define DH_ 64

// ---------------- scratch (no allocation allowed) ----------------
__device__ __align__(16) float g_q[(size_t)B_ * S_ * D_];
__device__ __align__(16) float g_k[(size_t)B_ * S_ * D_];
__device__ __align__(16) float g_v[(size_t)B_ * S_ * D_];
__device__ __align__(16) float g_o[(size_t)B_ * S_ * D_];

// ---------------- helpers ----------------
__device__ __forceinline__ uint32_t f2tf(float x) {  // fp32 -> tf32 bits (rna)
    uint32_t r;
    asm("cvt.rna.tf32.f32 %0, %1;" : "=r"(r) : "f"(x));
    return r;
}
__device__ __forceinline__ float f2tff(float x) { return __uint_as_float(f2tf(x)); }

// warp-level tf32 MMA: D(16x8) += A(16x8) * B(8x8), fp32 accum
__device__ __forceinline__ void mma8(float* d, const uint32_t* a,
                                     uint32_t b0, uint32_t b1) {
    asm volatile(
        "mma.sync.aligned.m16n8k8.row.col.f32.tf32.tf32.f32 "
        "{%0,%1,%2,%3}, {%4,%5,%6,%7}, {%8,%9}, {%0,%1,%2,%3};"
        : "+f"(d[0]), "+f"(d[1]), "+f"(d[2]), "+f"(d[3])
        : "r"(a[0]), "r"(a[1]), "r"(a[2]), "r"(a[3]), "r"(b0), "r"(b1));
}

// exp2 via magic-constant rounding + degree-4 poly. No F2I/F2F. err ~4e-5.
__device__ __forceinline__ float exp2_fast(float x) {
    x = fmaxf(x, -126.0f);
    float y = x + 12582912.0f;              // 1.5*2^23: RN-to-int in mantissa
    int n = __float_as_int(y);              // low bits hold round(x) (biased)
    float t = y - 12582912.0f;
    float f = x - t;                        // frac in [-0.5, 0.5]
    float p = fmaf(9.61813e-3f, f, 5.550411e-2f);
    p = fmaf(p, f, 2.4022651e-1f);
    p = fmaf(p, f, 6.9314718e-1f);
    p = fmaf(p, f, 1.0f);
    // (n<<23): bias bits of the magic constant shift out (low 9 bits are 0)
    return __int_as_float(__float_as_int(p) + (n << 23));
}

// ================= projection GEMM: C = relu(A[M,512] @ W[512,512] + b) =====
// Block 128x128, k-tile 32. 8 warps as 2(m) x 4(n); warp tile 64m x 32n.
#define AS_STR 36
#define WS_STR 136

__device__ __forceinline__ void gemm_mma_body(
    const float* __restrict__ A, const float* __restrict__ W,
    const float* __restrict__ bias, float* __restrict__ C,
    int bm, int bn)
{
    __shared__ float As[128 * AS_STR];  // A tile [128 m][32 k]
    __shared__ float Ws[32 * WS_STR];   // W tile [32 k][128 n]

    const int tid = threadIdx.x;
    const int lane = tid & 31;
    const int wid = tid >> 5;
    const int wm = wid >> 2;        // 0..1
    const int wn = wid & 3;         // 0..3
    const int g = lane >> 2;        // 0..7
    const int c = lane & 3;         // 0..3

    float acc[4][4][4];
    #pragma unroll
    for (int mt = 0; mt < 4; mt++)
        #pragma unroll
        for (int nt = 0; nt < 4; nt++)
            #pragma unroll
            for (int j = 0; j < 4; j++) acc[mt][nt][j] = 0.0f;

    float4 pa[4], pw[4];
    #pragma unroll
    for (int i = 0; i < 4; i++) {
        int idx = tid + i * 256;
        pa[i] = *(const float4*)(A + (size_t)(bm + (idx >> 3)) * D_ + (idx & 7) * 4);
        pw[i] = *(const float4*)(W + (size_t)(idx >> 5) * D_ + bn + (idx & 31) * 4);
    }

    for (int kt = 0; kt < 16; kt++) {
        __syncthreads();
        #pragma unroll
        for (int i = 0; i < 4; i++) {
            int idx = tid + i * 256;
            float4 a = pa[i], w = pw[i];
            a.x = f2tff(a.x); a.y = f2tff(a.y); a.z = f2tff(a.z); a.w = f2tff(a.w);
            w.x = f2tff(w.x); w.y = f2tff(w.y); w.z = f2tff(w.z); w.w = f2tff(w.w);
            *(float4*)&As[(idx >> 3) * AS_STR + (idx & 7) * 4] = a;
            *(float4*)&Ws[(idx >> 5) * WS_STR + (idx & 31) * 4] = w;
        }
        __syncthreads();

        if (kt < 15) {
            #pragma unroll
            for (int i = 0; i < 4; i++) {
                int idx = tid + i * 256;
                pa[i] = *(const float4*)(A + (size_t)(bm + (idx >> 3)) * D_ +
                                         (kt + 1) * 32 + (idx & 7) * 4);
                pw[i] = *(const float4*)(W + (size_t)((kt + 1) * 32 + (idx >> 5)) * D_ +
                                         bn + (idx & 31) * 4);
            }
        }

        #pragma unroll
        for (int ks = 0; ks < 4; ks++) {
            uint32_t af[4][4];
            #pragma unroll
            for (int mt = 0; mt < 4; mt++) {
                int mrow = wm * 64 + mt * 16 + g;
                int kk = ks * 8 + c;
                af[mt][0] = __float_as_uint(As[mrow * AS_STR + kk]);
                af[mt][1] = __float_as_uint(As[(mrow + 8) * AS_STR + kk]);
                af[mt][2] = __float_as_uint(As[mrow * AS_STR + kk + 4]);
                af[mt][3] = __float_as_uint(As[(mrow + 8) * AS_STR + kk + 4]);
            }
            #pragma unroll
            for (int nt = 0; nt < 4; nt++) {
                int ncol = wn * 32 + nt * 8 + g;
                int kk = ks * 8 + c;
                uint32_t b0 = __float_as_uint(Ws[kk * WS_STR + ncol]);
                uint32_t b1 = __float_as_uint(Ws[(kk + 4) * WS_STR + ncol]);
                #pragma unroll
                for (int mt = 0; mt < 4; mt++)
                    mma8(acc[mt][nt], af[mt], b0, b1);
            }
        }
    }

    #pragma unroll
    for (int mt = 0; mt < 4; mt++) {
        const int row = bm + wm * 64 + mt * 16 + g;
        #pragma unroll
        for (int nt = 0; nt < 4; nt++) {
            const int col = bn + wn * 32 + nt * 8 + 2 * c;
            const float b0 = bias[col], b1 = bias[col + 1];
            float2 v0, v1;
            v0.x = fmaxf(acc[mt][nt][0] + b0, 0.0f);
            v0.y = fmaxf(acc[mt][nt][1] + b1, 0.0f);
            v1.x = fmaxf(acc[mt][nt][2] + b0, 0.0f);
            v1.y = fmaxf(acc[mt][nt][3] + b1, 0.0f);
            *(float2*)(C + (size_t)row * D_ + col) = v0;
            *(float2*)(C + (size_t)(row + 8) * D_ + col) = v1;
        }
    }
}

__global__ void __launch_bounds__(256)
gemm_mma_qkv(const float* __restrict__ x,
             const float* __restrict__ Wq, const float* __restrict__ bq, float* __restrict__ Q,
             const float* __restrict__ Wk, const float* __restrict__ bk, float* __restrict__ K,
             const float* __restrict__ Wv, const float* __restrict__ bv, float* __restrict__ V)
{
    const float* W; const float* bias; float* C;
    if (blockIdx.z == 0)      { W = Wq; bias = bq; C = Q; }
    else if (blockIdx.z == 1) { W = Wk; bias = bk; C = K; }
    else                      { W = Wv; bias = bv; C = V; }
    gemm_mma_body(x, W, bias, C, blockIdx.y * 128, blockIdx.x * 128);
}

__global__ void __launch_bounds__(256)
gemm_mma_one(const float* __restrict__ A, const float* __restrict__ W,
             const float* __restrict__ bias, float* __restrict__ C)
{
    gemm_mma_body(A, W, bias, C, blockIdx.y * 128, blockIdx.x * 128);
}

// ================= flash attention with tf32 mma =================
// BM=64 q rows, BN=64 keys/tile, 128 threads (4 warps x 16m x 64n warp tiles).
// Small block -> 3 blocks/SM (occupancy), per-warp work unchanged.
#define AT_BM 64
#define PS_STR 68
#define KV_STR 72
// Ps[64][68] (also Q staging), Kts[64][72], Vs[64][72]
#define ATTN_SMEM_FLOATS (AT_BM * PS_STR + 2 * 64 * KV_STR)

__global__ void __launch_bounds__(128)
attn_mma(const float* __restrict__ Q, const float* __restrict__ K,
         const float* __restrict__ V, float* __restrict__ O)
{
    extern __shared__ float sm[];
    float* Ps  = sm;                         // [64][PS_STR]  m x key (and Q staging)
    float* Kts = sm + AT_BM * PS_STR;        // [64][KV_STR]  d x key (swizzled cols)
    float* Vs  = Kts + 64 * KV_STR;          // [64][KV_STR]  key x d

    const int tid = threadIdx.x;
    const int lane = tid & 31;
    const int wid = tid >> 5;
    const int g = lane >> 2;   // 0..7
    const int c = lane & 3;    // 0..3
    const int qblk = blockIdx.x;
    const int h = blockIdx.y;
    const int b = blockIdx.z;

    const float scale = 0.125f * 1.44269504f;  // 1/sqrt(64) * log2(e)

    // ---- prologue: stage Q (scaled, tf32) into Ps[m][d]
    {
        const float* qbase = Q + ((size_t)b * S_ + qblk * AT_BM) * D_ + h * DH_;
        #pragma unroll 4
        for (int it = 0; it < 8; it++) {
            int idx = tid + it * 128;        // 0..1023
            int mrow = idx >> 4;             // 0..63
            int d4 = (idx & 15) * 4;
            float4 t = *(const float4*)(qbase + (size_t)mrow * D_ + d4);
            t.x = f2tff(t.x * scale); t.y = f2tff(t.y * scale);
            t.z = f2tff(t.z * scale); t.w = f2tff(t.w * scale);
            *(float4*)&Ps[mrow * PS_STR + d4] = t;
        }
    }
    __syncthreads();

    // Q fragments to registers (reused every tile)
    const int prow0 = (wid * 16 + g) * PS_STR;
    const int prow1 = prow0 + 8 * PS_STR;
    uint32_t qf[8][4];
    #pragma unroll
    for (int ks = 0; ks < 8; ks++) {
        int kk = ks * 8 + c;
        qf[ks][0] = __float_as_uint(Ps[prow0 + kk]);
        qf[ks][1] = __float_as_uint(Ps[prow1 + kk]);
        qf[ks][2] = __float_as_uint(Ps[prow0 + kk + 4]);
        qf[ks][3] = __float_as_uint(Ps[prow1 + kk + 4]);
    }

    float o[8][4];
    #pragma unroll
    for (int nt = 0; nt < 8; nt++)
        #pragma unroll
        for (int j = 0; j < 4; j++) o[nt][j] = 0.0f;
    float m0 = -1e30f, m1 = -1e30f, l0 = 0.0f, l1 = 0.0f;

    const size_t kvbase = (size_t)b * S_ * D_ + h * DH_;

    for (int t0 = 0; t0 < S_; t0 += 64) {
        __syncthreads();  // all prior frag reads done (also covers prologue)

        // ---- stage K transposed (swizzled) + V natural, tf32
        #pragma unroll 4
        for (int it = 0; it < 8; it++) {
            int idx = tid + it * 128;
            int n = idx >> 4;              // key 0..63
            int d4 = (idx & 15) * 4;
            size_t goff = kvbase + (size_t)(t0 + n) * D_ + d4;
            float4 kv = *(const float4*)(K + goff);
            float4 vv = *(const float4*)(V + goff);
            int swz = ((d4 >> 2) & 15) * 2;      // uniform over the 4 d's
            int nsw = n ^ swz;
            Kts[(d4 + 0) * KV_STR + nsw] = f2tff(kv.x);
            Kts[(d4 + 1) * KV_STR + nsw] = f2tff(kv.y);
            Kts[(d4 + 2) * KV_STR + nsw] = f2tff(kv.z);
            Kts[(d4 + 3) * KV_STR + nsw] = f2tff(kv.w);
            vv.x = f2tff(vv.x); vv.y = f2tff(vv.y);
            vv.z = f2tff(vv.z); vv.w = f2tff(vv.w);
            *(float4*)&Vs[n * KV_STR + d4] = vv;
        }
        __syncthreads();

        // ---- S = Q @ K^T  (warp: 16 rows x 64 keys)
        float sacc[8][4];
        #pragma unroll
        for (int nt = 0; nt < 8; nt++)
            #pragma unroll
            for (int j = 0; j < 4; j++) sacc[nt][j] = 0.0f;

        #pragma unroll
        for (int ks = 0; ks < 8; ks++) {
            int k0 = ks * 8 + c;
            int swz0 = ((k0 >> 2) & 15) * 2;
            int swz1 = (((k0 + 4) >> 2) & 15) * 2;
            #pragma unroll
            for (int nt = 0; nt < 8; nt++) {
                int col = nt * 8 + g;
                uint32_t b0 = __float_as_uint(Kts[k0 * KV_STR + (col ^ swz0)]);
                uint32_t b1 = __float_as_uint(Kts[(k0 + 4) * KV_STR + (col ^ swz1)]);
                mma8(sacc[nt], qf[ks], b0, b1);
            }
        }

        // ---- online softmax (log2 domain); thread owns rows g and g+8
        float tm0 = -1e30f, tm1 = -1e30f;
        #pragma unroll
        for (int nt = 0; nt < 8; nt++) {
            tm0 = fmaxf(tm0, fmaxf(sacc[nt][0], sacc[nt][1]));
            tm1 = fmaxf(tm1, fmaxf(sacc[nt][2], sacc[nt][3]));
        }
        tm0 = fmaxf(tm0, __shfl_xor_sync(0xffffffff, tm0, 1));
        tm0 = fmaxf(tm0, __shfl_xor_sync(0xffffffff, tm0, 2));
        tm1 = fmaxf(tm1, __shfl_xor_sync(0xffffffff, tm1, 1));
        tm1 = fmaxf(tm1, __shfl_xor_sync(0xffffffff, tm1, 2));

        float mn0 = fmaxf(m0, tm0), mn1 = fmaxf(m1, tm1);
        float corr0 = exp2_fast(m0 - mn0), corr1 = exp2_fast(m1 - mn1);
        m0 = mn0; m1 = mn1;

        float rs0 = 0.0f, rs1 = 0.0f;
        #pragma unroll
        for (int nt = 0; nt < 8; nt++) {
            sacc[nt][0] = exp2_fast(sacc[nt][0] - m0);
            sacc[nt][1] = exp2_fast(sacc[nt][1] - m0);
            sacc[nt][2] = exp2_fast(sacc[nt][2] - m1);
            sacc[nt][3] = exp2_fast(sacc[nt][3] - m1);
            rs0 += sacc[nt][0] + sacc[nt][1];
            rs1 += sacc[nt][2] + sacc[nt][3];
        }
        rs0 += __shfl_xor_sync(0xffffffff, rs0, 1);
        rs0 += __shfl_xor_sync(0xffffffff, rs0, 2);
        rs1 += __shfl_xor_sync(0xffffffff, rs1, 1);
        rs1 += __shfl_xor_sync(0xffffffff, rs1, 2);
        l0 = l0 * corr0 + rs0;
        l1 = l1 * corr1 + rs1;
        #pragma unroll
        for (int nt = 0; nt < 8; nt++) {
            o[nt][0] *= corr0; o[nt][1] *= corr0;
            o[nt][2] *= corr1; o[nt][3] *= corr1;
        }

        // ---- store P fragments into Ps[m][key]; warp-private rows.
        // (no tf32 cvt: MMA truncation adds ~1e-4 err, within budget)
        #pragma unroll
        for (int nt = 0; nt < 8; nt++) {
            float2 p01, p23;
            p01.x = sacc[nt][0]; p01.y = sacc[nt][1];
            p23.x = sacc[nt][2]; p23.y = sacc[nt][3];
            *(float2*)&Ps[prow0 + nt * 8 + 2 * c] = p01;
            *(float2*)&Ps[prow1 + nt * 8 + 2 * c] = p23;
        }
        __syncwarp();

        // ---- O += P @ V  (A from Ps, B from Vs)
        #pragma unroll
        for (int ks = 0; ks < 8; ks++) {
            int kk = ks * 8 + c;
            uint32_t af[4];
            af[0] = __float_as_uint(Ps[prow0 + kk]);
            af[1] = __float_as_uint(Ps[prow1 + kk]);
            af[2] = __float_as_uint(Ps[prow0 + kk + 4]);
            af[3] = __float_as_uint(Ps[prow1 + kk + 4]);
            #pragma unroll
            for (int nt = 0; nt < 8; nt++) {
                int col = nt * 8 + g;
                uint32_t b0 = __float_as_uint(Vs[kk * KV_STR + col]);
                uint32_t b1 = __float_as_uint(Vs[(kk + 4) * KV_STR + col]);
                mma8(o[nt], af, b0, b1);
            }
        }
    }

    // ---- epilogue
    const float inv0 = 1.0f / l0, inv1 = 1.0f / l1;
    float* obase = O + ((size_t)b * S_ + qblk * AT_BM + wid * 16 + g) * D_ + h * DH_;
    #pragma unroll
    for (int nt = 0; nt < 8; nt++) {
        float2 v0, v1;
        v0.x = o[nt][0] * inv0; v0.y = o[nt][1] * inv0;
        v1.x = o[nt][2] * inv1; v1.y = o[nt][3] * inv1;
        *(float2*)(obase + nt * 8 + 2 * c) = v0;
        *(float2*)(obase + (size_t)8 * D_ + nt * 8 + 2 * c) = v1;
    }
}

// ---------------- launch ----------------
extern "C" void kernel_launch(void* const* d_in, const int* in_sizes, int n_in,
                              void* d_out, int out_size)
{
    const float* x  = (const float*)d_in[0];
    const float* Wq = (const float*)d_in[1];
    const float* bq = (const float*)d_in[2];
    const float* Wk = (const float*)d_in[3];
    const float* bk = (const float*)d_in[4];
    const float* Wv = (const float*)d_in[5];
    const float* bv = (const float*)d_in[6];
    const float* Wo = (const float*)d_in[7];
    const float* bo = (const float*)d_in[8];
    float* out = (float*)d_out;

    float *Qb, *Kb, *Vb, *Ob;
    cudaGetSymbolAddress((void**)&Qb, g_q);
    cudaGetSymbolAddress((void**)&Kb, g_k);
    cudaGetSymbolAddress((void**)&Vb, g_v);
    cudaGetSymbolAddress((void**)&Ob, g_o);

    dim3 qkv_grid(D_ / 128, (B_ * S_) / 128, 3);   // (4, 64, 3)
    gemm_mma_qkv<<<qkv_grid, 256>>>(x, Wq, bq, Qb, Wk, bk, Kb, Wv, bv, Vb);

    const int attn_smem = ATTN_SMEM_FLOATS * (int)sizeof(float);  // 54272 B
    cudaFuncSetAttribute(attn_mma, cudaFuncAttributeMaxDynamicSharedMemorySize,
                         attn_smem);
    dim3 agrid(S_ / AT_BM, H_, B_);  // (64, 8, 2) = 1024 blocks
    attn_mma<<<agrid, 128, attn_smem>>>(Qb, Kb, Vb, Ob);

    dim3 ogrid(D_ / 128, (B_ * S_) / 128);         // (4, 64)
    gemm_mma_one<<<ogrid, 256>>>(Ob, Wo, bo, out);
}

// round 7
// speedup vs baseline: 4.5366x; 1.1359x over previous
#include <cuda_runtime.h>
#include <cuda_fp16.h>
#include <cstddef>
#include <cstdint>

// Problem constants
#define B_ 2
#define S_ 4096
#define D_ 512
#define H_ 8
#define DH_ 64

// ---------------- scratch (no allocation allowed) ----------------
__device__ __align__(16) float g_q[(size_t)B_ * S_ * D_];
__device__ __align__(16) float g_k[(size_t)B_ * S_ * D_];
__device__ __align__(16) float g_v[(size_t)B_ * S_ * D_];
__device__ __align__(16) float g_o[(size_t)B_ * S_ * D_];

// ---------------- helpers ----------------
__device__ __forceinline__ uint32_t f2tf(float x) {  // fp32 -> tf32 bits (rna)
    uint32_t r;
    asm("cvt.rna.tf32.f32 %0, %1;" : "=r"(r) : "f"(x));
    return r;
}
__device__ __forceinline__ float f2tff(float x) { return __uint_as_float(f2tf(x)); }

__device__ __forceinline__ uint32_t h2pack(float lo, float hi) {
    __half2 h = __floats2half2_rn(lo, hi);
    return *(uint32_t*)&h;
}

// tf32 MMA: D(16x8) += A(16x8) * B(8x8)
__device__ __forceinline__ void mma8(float* d, const uint32_t* a,
                                     uint32_t b0, uint32_t b1) {
    asm volatile(
        "mma.sync.aligned.m16n8k8.row.col.f32.tf32.tf32.f32 "
        "{%0,%1,%2,%3}, {%4,%5,%6,%7}, {%8,%9}, {%0,%1,%2,%3};"
        : "+f"(d[0]), "+f"(d[1]), "+f"(d[2]), "+f"(d[3])
        : "r"(a[0]), "r"(a[1]), "r"(a[2]), "r"(a[3]), "r"(b0), "r"(b1));
}
// fp16 MMA: D(16x8) += A(16x16) * B(16x8), fp32 accum
__device__ __forceinline__ void mma16(float* d, const uint32_t* a,
                                      uint32_t b0, uint32_t b1) {
    asm volatile(
        "mma.sync.aligned.m16n8k16.row.col.f32.f16.f16.f32 "
        "{%0,%1,%2,%3}, {%4,%5,%6,%7}, {%8,%9}, {%0,%1,%2,%3};"
        : "+f"(d[0]), "+f"(d[1]), "+f"(d[2]), "+f"(d[3])
        : "r"(a[0]), "r"(a[1]), "r"(a[2]), "r"(a[3]), "r"(b0), "r"(b1));
}

// exp2 via magic-constant rounding + degree-4 poly. No F2I/F2F.
__device__ __forceinline__ float exp2_fast(float x) {
    x = fmaxf(x, -126.0f);
    float y = x + 12582912.0f;              // 1.5*2^23: RN-to-int in mantissa
    int n = __float_as_int(y);
    float t = y - 12582912.0f;
    float f = x - t;                        // frac in [-0.5, 0.5]
    float p = fmaf(9.61813e-3f, f, 5.550411e-2f);
    p = fmaf(p, f, 2.4022651e-1f);
    p = fmaf(p, f, 6.9314718e-1f);
    p = fmaf(p, f, 1.0f);
    return __int_as_float(__float_as_int(p) + (n << 23));
}

// ================= projection GEMM: C = relu(A[M,512] @ W[512,512] + b) =====
// (unchanged tf32 path: one variable at a time)
#define AS_STR 36
#define WS_STR 136

__device__ __forceinline__ void gemm_mma_body(
    const float* __restrict__ A, const float* __restrict__ W,
    const float* __restrict__ bias, float* __restrict__ C,
    int bm, int bn)
{
    __shared__ float As[128 * AS_STR];  // A tile [128 m][32 k]
    __shared__ float Ws[32 * WS_STR];   // W tile [32 k][128 n]

    const int tid = threadIdx.x;
    const int lane = tid & 31;
    const int wid = tid >> 5;
    const int wm = wid >> 2;
    const int wn = wid & 3;
    const int g = lane >> 2;
    const int c = lane & 3;

    float acc[4][4][4];
    #pragma unroll
    for (int mt = 0; mt < 4; mt++)
        #pragma unroll
        for (int nt = 0; nt < 4; nt++)
            #pragma unroll
            for (int j = 0; j < 4; j++) acc[mt][nt][j] = 0.0f;

    float4 pa[4], pw[4];
    #pragma unroll
    for (int i = 0; i < 4; i++) {
        int idx = tid + i * 256;
        pa[i] = *(const float4*)(A + (size_t)(bm + (idx >> 3)) * D_ + (idx & 7) * 4);
        pw[i] = *(const float4*)(W + (size_t)(idx >> 5) * D_ + bn + (idx & 31) * 4);
    }

    for (int kt = 0; kt < 16; kt++) {
        __syncthreads();
        #pragma unroll
        for (int i = 0; i < 4; i++) {
            int idx = tid + i * 256;
            float4 a = pa[i], w = pw[i];
            a.x = f2tff(a.x); a.y = f2tff(a.y); a.z = f2tff(a.z); a.w = f2tff(a.w);
            w.x = f2tff(w.x); w.y = f2tff(w.y); w.z = f2tff(w.z); w.w = f2tff(w.w);
            *(float4*)&As[(idx >> 3) * AS_STR + (idx & 7) * 4] = a;
            *(float4*)&Ws[(idx >> 5) * WS_STR + (idx & 31) * 4] = w;
        }
        __syncthreads();

        if (kt < 15) {
            #pragma unroll
            for (int i = 0; i < 4; i++) {
                int idx = tid + i * 256;
                pa[i] = *(const float4*)(A + (size_t)(bm + (idx >> 3)) * D_ +
                                         (kt + 1) * 32 + (idx & 7) * 4);
                pw[i] = *(const float4*)(W + (size_t)((kt + 1) * 32 + (idx >> 5)) * D_ +
                                         bn + (idx & 31) * 4);
            }
        }

        #pragma unroll
        for (int ks = 0; ks < 4; ks++) {
            uint32_t af[4][4];
            #pragma unroll
            for (int mt = 0; mt < 4; mt++) {
                int mrow = wm * 64 + mt * 16 + g;
                int kk = ks * 8 + c;
                af[mt][0] = __float_as_uint(As[mrow * AS_STR + kk]);
                af[mt][1] = __float_as_uint(As[(mrow + 8) * AS_STR + kk]);
                af[mt][2] = __float_as_uint(As[mrow * AS_STR + kk + 4]);
                af[mt][3] = __float_as_uint(As[(mrow + 8) * AS_STR + kk + 4]);
            }
            #pragma unroll
            for (int nt = 0; nt < 4; nt++) {
                int ncol = wn * 32 + nt * 8 + g;
                int kk = ks * 8 + c;
                uint32_t b0 = __float_as_uint(Ws[kk * WS_STR + ncol]);
                uint32_t b1 = __float_as_uint(Ws[(kk + 4) * WS_STR + ncol]);
                #pragma unroll
                for (int mt = 0; mt < 4; mt++)
                    mma8(acc[mt][nt], af[mt], b0, b1);
            }
        }
    }

    #pragma unroll
    for (int mt = 0; mt < 4; mt++) {
        const int row = bm + wm * 64 + mt * 16 + g;
        #pragma unroll
        for (int nt = 0; nt < 4; nt++) {
            const int col = bn + wn * 32 + nt * 8 + 2 * c;
            const float b0 = bias[col], b1 = bias[col + 1];
            float2 v0, v1;
            v0.x = fmaxf(acc[mt][nt][0] + b0, 0.0f);
            v0.y = fmaxf(acc[mt][nt][1] + b1, 0.0f);
            v1.x = fmaxf(acc[mt][nt][2] + b0, 0.0f);
            v1.y = fmaxf(acc[mt][nt][3] + b1, 0.0f);
            *(float2*)(C + (size_t)row * D_ + col) = v0;
            *(float2*)(C + (size_t)(row + 8) * D_ + col) = v1;
        }
    }
}

__global__ void __launch_bounds__(256)
gemm_mma_qkv(const float* __restrict__ x,
             const float* __restrict__ Wq, const float* __restrict__ bq, float* __restrict__ Q,
             const float* __restrict__ Wk, const float* __restrict__ bk, float* __restrict__ K,
             const float* __restrict__ Wv, const float* __restrict__ bv, float* __restrict__ V)
{
    const float* W; const float* bias; float* C;
    if (blockIdx.z == 0)      { W = Wq; bias = bq; C = Q; }
    else if (blockIdx.z == 1) { W = Wk; bias = bk; C = K; }
    else                      { W = Wv; bias = bv; C = V; }
    gemm_mma_body(x, W, bias, C, blockIdx.y * 128, blockIdx.x * 128);
}

__global__ void __launch_bounds__(256)
gemm_mma_one(const float* __restrict__ A, const float* __restrict__ W,
             const float* __restrict__ bias, float* __restrict__ C)
{
    gemm_mma_body(A, W, bias, C, blockIdx.y * 128, blockIdx.x * 128);
}

// ================= flash attention, fp16 m16n8k16 =================
// BM=64 q rows, BN=64 keys/tile, 128 threads (4 warps, 16m x 64n each).
// All smem in half2 (uint32), row stride 36 -> bank (4g+c): conflict-free.
#define AT_BM 64
#define HSTR 36

__global__ void __launch_bounds__(128, 4)
attn_mma(const float* __restrict__ Q, const float* __restrict__ K,
         const float* __restrict__ V, float* __restrict__ O)
{
    __shared__ uint32_t Qh[AT_BM * HSTR];  // [m][d-pair]
    __shared__ uint32_t Kh[64 * HSTR];     // [key][d-pair]
    __shared__ uint32_t Vp[64 * HSTR];     // [d][key-pair]

    const int tid = threadIdx.x;
    const int lane = tid & 31;
    const int wid = tid >> 5;
    const int g = lane >> 2;   // 0..7
    const int c = lane & 3;    // 0..3
    const int qblk = blockIdx.x;
    const int h = blockIdx.y;
    const int b = blockIdx.z;

    const float scale = 0.125f * 1.44269504f;  // 1/sqrt(64) * log2(e)

    // ---- prologue: stage Q (scaled, fp16-packed) into Qh[m][d-pair]
    {
        const float* qbase = Q + ((size_t)b * S_ + qblk * AT_BM) * D_ + h * DH_;
        #pragma unroll 4
        for (int it = 0; it < 8; it++) {
            int idx = tid + it * 128;        // 0..1023
            int m = idx >> 4;                // 0..63
            int q = idx & 15;                // d-quad
            float4 t = *(const float4*)(qbase + (size_t)m * D_ + q * 4);
            uint2 u;
            u.x = h2pack(t.x * scale, t.y * scale);
            u.y = h2pack(t.z * scale, t.w * scale);
            *(uint2*)&Qh[m * HSTR + 2 * q] = u;
        }
    }
    __syncthreads();

    // Q fragments to registers, once (a-frags for 4 k-chunks of 16 d)
    uint32_t qf[4][4];
    {
        const int r0 = (wid * 16 + g) * HSTR;
        const int r1 = r0 + 8 * HSTR;
        #pragma unroll
        for (int kc = 0; kc < 4; kc++) {
            qf[kc][0] = Qh[r0 + 8 * kc + c];
            qf[kc][1] = Qh[r1 + 8 * kc + c];
            qf[kc][2] = Qh[r0 + 8 * kc + 4 + c];
            qf[kc][3] = Qh[r1 + 8 * kc + 4 + c];
        }
    }

    float o[8][4];
    #pragma unroll
    for (int nt = 0; nt < 8; nt++)
        #pragma unroll
        for (int j = 0; j < 4; j++) o[nt][j] = 0.0f;
    float m0 = -1e30f, m1 = -1e30f, l0 = 0.0f, l1 = 0.0f;

    const size_t kvbase = (size_t)b * S_ * D_ + h * DH_;

    for (int t0 = 0; t0 < S_; t0 += 64) {
        __syncthreads();  // prior tile's fragment LDS done before overwrite

        // ---- stage K: [key][d-pair]
        #pragma unroll 4
        for (int it = 0; it < 8; it++) {
            int idx = tid + it * 128;
            int n = idx >> 4;              // key 0..63
            int q = idx & 15;
            float4 kv = *(const float4*)(K + kvbase + (size_t)(t0 + n) * D_ + q * 4);
            uint2 u;
            u.x = h2pack(kv.x, kv.y);
            u.y = h2pack(kv.z, kv.w);
            *(uint2*)&Kh[n * HSTR + 2 * q] = u;
        }
        // ---- stage V transposed: [d][key-pair]
        #pragma unroll 2
        for (int it = 0; it < 4; it++) {
            int idx = tid + it * 128;      // 0..511
            int p = idx & 31;              // key-pair 0..31
            int dq = idx >> 5;             // d-quad 0..15
            const float* va = V + kvbase + (size_t)(t0 + 2 * p) * D_ + dq * 4;
            float4 a = *(const float4*)va;
            float4 bb = *(const float4*)(va + D_);
            Vp[(4 * dq + 0) * HSTR + p] = h2pack(a.x, bb.x);
            Vp[(4 * dq + 1) * HSTR + p] = h2pack(a.y, bb.y);
            Vp[(4 * dq + 2) * HSTR + p] = h2pack(a.z, bb.z);
            Vp[(4 * dq + 3) * HSTR + p] = h2pack(a.w, bb.w);
        }
        __syncthreads();

        // ---- S = Q @ K^T  (warp: 16 rows x 64 keys, 4 k-chunks of 16 d)
        float sacc[8][4];
        #pragma unroll
        for (int nt = 0; nt < 8; nt++)
            #pragma unroll
            for (int j = 0; j < 4; j++) sacc[nt][j] = 0.0f;

        #pragma unroll
        for (int kc = 0; kc < 4; kc++) {
            #pragma unroll
            for (int nt = 0; nt < 8; nt++) {
                const int base = (nt * 8 + g) * HSTR + 8 * kc + c;
                uint32_t b0 = Kh[base];
                uint32_t b1 = Kh[base + 4];
                mma16(sacc[nt], qf[kc], b0, b1);
            }
        }

        // ---- online softmax (log2 domain); thread owns rows g and g+8
        float tm0 = -1e30f, tm1 = -1e30f;
        #pragma unroll
        for (int nt = 0; nt < 8; nt++) {
            tm0 = fmaxf(tm0, fmaxf(sacc[nt][0], sacc[nt][1]));
            tm1 = fmaxf(tm1, fmaxf(sacc[nt][2], sacc[nt][3]));
        }
        tm0 = fmaxf(tm0, __shfl_xor_sync(0xffffffff, tm0, 1));
        tm0 = fmaxf(tm0, __shfl_xor_sync(0xffffffff, tm0, 2));
        tm1 = fmaxf(tm1, __shfl_xor_sync(0xffffffff, tm1, 1));
        tm1 = fmaxf(tm1, __shfl_xor_sync(0xffffffff, tm1, 2));

        float mn0 = fmaxf(m0, tm0), mn1 = fmaxf(m1, tm1);
        float corr0 = exp2_fast(m0 - mn0), corr1 = exp2_fast(m1 - mn1);
        m0 = mn0; m1 = mn1;

        float rs0 = 0.0f, rs1 = 0.0f;
        #pragma unroll
        for (int nt = 0; nt < 8; nt++) {
            sacc[nt][0] = exp2_fast(sacc[nt][0] - m0);
            sacc[nt][1] = exp2_fast(sacc[nt][1] - m0);
            sacc[nt][2] = exp2_fast(sacc[nt][2] - m1);
            sacc[nt][3] = exp2_fast(sacc[nt][3] - m1);
            rs0 += sacc[nt][0] + sacc[nt][1];
            rs1 += sacc[nt][2] + sacc[nt][3];
        }
        rs0 += __shfl_xor_sync(0xffffffff, rs0, 1);
        rs0 += __shfl_xor_sync(0xffffffff, rs0, 2);
        rs1 += __shfl_xor_sync(0xffffffff, rs1, 1);
        rs1 += __shfl_xor_sync(0xffffffff, rs1, 2);
        l0 = l0 * corr0 + rs0;
        l1 = l1 * corr1 + rs1;
        #pragma unroll
        for (int nt = 0; nt < 8; nt++) {
            o[nt][0] *= corr0; o[nt][1] *= corr0;
            o[nt][2] *= corr1; o[nt][3] *= corr1;
        }

        // ---- O += P @ V. P's D-fragment IS the fp16 A-fragment after packing:
        // no smem round-trip, no syncwarp.
        #pragma unroll
        for (int kc = 0; kc < 4; kc++) {
            uint32_t af[4];
            af[0] = h2pack(sacc[2 * kc][0], sacc[2 * kc][1]);
            af[1] = h2pack(sacc[2 * kc][2], sacc[2 * kc][3]);
            af[2] = h2pack(sacc[2 * kc + 1][0], sacc[2 * kc + 1][1]);
            af[3] = h2pack(sacc[2 * kc + 1][2], sacc[2 * kc + 1][3]);
            #pragma unroll
            for (int nt = 0; nt < 8; nt++) {
                const int base = (nt * 8 + g) * HSTR + 8 * kc + c;
                uint32_t b0 = Vp[base];
                uint32_t b1 = Vp[base + 4];
                mma16(o[nt], af, b0, b1);
            }
        }
    }

    // ---- epilogue
    const float inv0 = 1.0f / l0, inv1 = 1.0f / l1;
    float* obase = O + ((size_t)b * S_ + qblk * AT_BM + wid * 16 + g) * D_ + h * DH_;
    #pragma unroll
    for (int nt = 0; nt < 8; nt++) {
        float2 v0, v1;
        v0.x = o[nt][0] * inv0; v0.y = o[nt][1] * inv0;
        v1.x = o[nt][2] * inv1; v1.y = o[nt][3] * inv1;
        *(float2*)(obase + nt * 8 + 2 * c) = v0;
        *(float2*)(obase + (size_t)8 * D_ + nt * 8 + 2 * c) = v1;
    }
}

// ---------------- launch ----------------
extern "C" void kernel_launch(void* const* d_in, const int* in_sizes, int n_in,
                              void* d_out, int out_size)
{
    const float* x  = (const float*)d_in[0];
    const float* Wq = (const float*)d_in[1];
    const float* bq = (const float*)d_in[2];
    const float* Wk = (const float*)d_in[3];
    const float* bk = (const float*)d_in[4];
    const float* Wv = (const float*)d_in[5];
    const float* bv = (const float*)d_in[6];
    const float* Wo = (const float*)d_in[7];
    const float* bo = (const float*)d_in[8];
    float* out = (float*)d_out;

    float *Qb, *Kb, *Vb, *Ob;
    cudaGetSymbolAddress((void**)&Qb, g_q);
    cudaGetSymbolAddress((void**)&Kb, g_k);
    cudaGetSymbolAddress((void**)&Vb, g_v);
    cudaGetSymbolAddress((void**)&Ob, g_o);

    dim3 qkv_grid(D_ / 128, (B_ * S_) / 128, 3);   // (4, 64, 3)
    gemm_mma_qkv<<<qkv_grid, 256>>>(x, Wq, bq, Qb, Wk, bk, Kb, Wv, bv, Vb);

    dim3 agrid(S_ / AT_BM, H_, B_);  // (64, 8, 2) = 1024 blocks
    attn_mma<<<agrid, 128>>>(Qb, Kb, Vb, Ob);

    dim3 ogrid(D_ / 128, (B_ * S_) / 128);         // (4, 64)
    gemm_mma_one<<<ogrid, 256>>>(Ob, Wo, bo, out);
}

// round 8
// speedup vs baseline: 8.2616x; 1.8211x over previous
#include <cuda_runtime.h>
#include <cuda_fp16.h>
#include <cstddef>
#include <cstdint>

// Problem constants
#define B_ 2
#define S_ 4096
#define D_ 512
#define H_ 8
#define DH_ 64
#define NP_ 256   // pairs per row (D_/2)

// ---------------- scratch (no allocation allowed) ----------------
__device__ __align__(16) uint32_t g_xh[(size_t)B_ * S_ * NP_];
__device__ __align__(16) uint32_t g_qh[(size_t)B_ * S_ * NP_];
__device__ __align__(16) uint32_t g_kh[(size_t)B_ * S_ * NP_];
__device__ __align__(16) uint32_t g_vh[(size_t)B_ * S_ * NP_];
__device__ __align__(16) uint32_t g_oh[(size_t)B_ * S_ * NP_];

// ---------------- helpers ----------------
__device__ __forceinline__ uint32_t smem_u32(const void* p) {
    uint32_t a;
    asm("{ .reg .u64 t; cvta.to.shared.u64 t, %1; cvt.u32.u64 %0, t; }"
        : "=r"(a) : "l"(p));
    return a;
}
__device__ __forceinline__ uint32_t h2pack(float lo, float hi) {
    __half2 h = __floats2half2_rn(lo, hi);
    return *(uint32_t*)&h;
}
__device__ __forceinline__ uint32_t hmul2u(uint32_t a, __half2 s) {
    __half2 r = __hmul2(*(__half2*)&a, s);
    return *(uint32_t*)&r;
}

// fp16 MMA: D(16x8) += A(16x16) * B(16x8), fp32 accum
__device__ __forceinline__ void mma16(float* d, const uint32_t* a,
                                      uint32_t b0, uint32_t b1) {
    asm volatile(
        "mma.sync.aligned.m16n8k16.row.col.f32.f16.f16.f32 "
        "{%0,%1,%2,%3}, {%4,%5,%6,%7}, {%8,%9}, {%0,%1,%2,%3};"
        : "+f"(d[0]), "+f"(d[1]), "+f"(d[2]), "+f"(d[3])
        : "r"(a[0]), "r"(a[1]), "r"(a[2]), "r"(a[3]), "r"(b0), "r"(b1));
}

#define LDMX4(r0, r1, r2, r3, addr)                                        \
    asm volatile("ldmatrix.sync.aligned.m8n8.x4.shared.b16 "               \
                 "{%0,%1,%2,%3}, [%4];"                                    \
                 : "=r"(r0), "=r"(r1), "=r"(r2), "=r"(r3) : "r"(addr))
#define LDMX4T(r0, r1, r2, r3, addr)                                       \
    asm volatile("ldmatrix.sync.aligned.m8n8.x4.trans.shared.b16 "         \
                 "{%0,%1,%2,%3}, [%4];"                                    \
                 : "=r"(r0), "=r"(r1), "=r"(r2), "=r"(r3) : "r"(addr))

// exp2 via magic-constant rounding + degree-4 poly.
__device__ __forceinline__ float exp2_fast(float x) {
    x = fmaxf(x, -126.0f);
    float y = x + 12582912.0f;
    int n = __float_as_int(y);
    float t = y - 12582912.0f;
    float f = x - t;
    float p = fmaf(9.61813e-3f, f, 5.550411e-2f);
    p = fmaf(p, f, 2.4022651e-1f);
    p = fmaf(p, f, 6.9314718e-1f);
    p = fmaf(p, f, 1.0f);
    return __int_as_float(__float_as_int(p) + (n << 23));
}

// ================= x -> half pairs =================
__global__ void __launch_bounds__(256)
cvt_x(const float4* __restrict__ x, uint4* __restrict__ xh)
{
    size_t i = (size_t)blockIdx.x * 256 + threadIdx.x;
    float4 a = x[2 * i], b = x[2 * i + 1];
    uint4 o;
    o.x = h2pack(a.x, a.y); o.y = h2pack(a.z, a.w);
    o.z = h2pack(b.x, b.y); o.w = h2pack(b.z, b.w);
    xh[i] = o;
}

// ================= fp16 GEMM: C = relu(Ah[M,512] @ W[512,512] + b) =========
// Block 128m x 128n, k-tile 32. 8 warps 2m x 4n, warp tile 64m x 32n.
// Ah smem [128 m][16 kp + 4 pad]; Wh smem [16 kp][128 n + 8 pad] (pairs over k).
#define GA_STR 20
#define GW_STR 136

template <int OUT_HALF>
__device__ __forceinline__ void gemm_h_body(
    const uint32_t* __restrict__ Ah_g,   // [M][256] half pairs
    const float* __restrict__ W,         // [512][512] fp32
    const float* __restrict__ bias,
    void* __restrict__ Cout,
    int bm, int bn)
{
    __shared__ __align__(16) uint32_t Ah[128 * GA_STR];
    __shared__ __align__(16) uint32_t Wh[16 * GW_STR];

    const int tid = threadIdx.x;
    const int lane = tid & 31;
    const int wid = tid >> 5;
    const int wm = wid >> 2;
    const int wn = wid & 3;
    const int g = lane >> 2;
    const int c = lane & 3;

    float acc[4][4][4];
    #pragma unroll
    for (int mt = 0; mt < 4; mt++)
        #pragma unroll
        for (int nt = 0; nt < 4; nt++)
            #pragma unroll
            for (int j = 0; j < 4; j++) acc[mt][nt][j] = 0.0f;

    // staging maps
    const int am = (tid + 0) >> 2, ach = tid & 3;          // + i*256 below
    const int wkp = tid >> 5 >= 0 ? 0 : 0;                 // (computed inline)

    uint4 pa[2];
    float4 pw[4];
    #pragma unroll
    for (int i = 0; i < 2; i++) {
        int idx = tid + i * 256;
        int m = idx >> 2, ch = idx & 3;
        pa[i] = *(const uint4*)(Ah_g + (size_t)(bm + m) * NP_ + 4 * ch);
        int kp = idx >> 5, n4 = idx & 31;
        pw[2 * i]     = *(const float4*)(W + (size_t)(2 * kp) * D_ + bn + 4 * n4);
        pw[2 * i + 1] = *(const float4*)(W + (size_t)(2 * kp + 1) * D_ + bn + 4 * n4);
    }

    for (int kt = 0; kt < 16; kt++) {
        __syncthreads();
        #pragma unroll
        for (int i = 0; i < 2; i++) {
            int idx = tid + i * 256;
            int m = idx >> 2, ch = idx & 3;
            *(uint4*)&Ah[m * GA_STR + 4 * ch] = pa[i];
            int kp = idx >> 5, n4 = idx & 31;
            uint4 wv;
            wv.x = h2pack(pw[2 * i].x, pw[2 * i + 1].x);
            wv.y = h2pack(pw[2 * i].y, pw[2 * i + 1].y);
            wv.z = h2pack(pw[2 * i].z, pw[2 * i + 1].z);
            wv.w = h2pack(pw[2 * i].w, pw[2 * i + 1].w);
            *(uint4*)&Wh[kp * GW_STR + 4 * n4] = wv;
        }
        __syncthreads();

        if (kt < 15) {
            #pragma unroll
            for (int i = 0; i < 2; i++) {
                int idx = tid + i * 256;
                int m = idx >> 2, ch = idx & 3;
                pa[i] = *(const uint4*)(Ah_g + (size_t)(bm + m) * NP_ +
                                        (kt + 1) * 16 + 4 * ch);
                int kp = idx >> 5, n4 = idx & 31;
                pw[2 * i]     = *(const float4*)(W + (size_t)((kt + 1) * 32 + 2 * kp) * D_ + bn + 4 * n4);
                pw[2 * i + 1] = *(const float4*)(W + (size_t)((kt + 1) * 32 + 2 * kp + 1) * D_ + bn + 4 * n4);
            }
        }

        #pragma unroll
        for (int kc = 0; kc < 2; kc++) {
            uint32_t af[4][4];
            #pragma unroll
            for (int mt = 0; mt < 4; mt++) {
                int base = (wm * 64 + mt * 16 + g) * GA_STR + kc * 8 + c;
                af[mt][0] = Ah[base];
                af[mt][1] = Ah[base + 8 * GA_STR];
                af[mt][2] = Ah[base + 4];
                af[mt][3] = Ah[base + 8 * GA_STR + 4];
            }
            #pragma unroll
            for (int nt = 0; nt < 4; nt++) {
                int rb = (kc * 8 + c) * GW_STR + wn * 32 + nt * 8 + g;
                uint32_t b0 = Wh[rb];
                uint32_t b1 = Wh[rb + 4 * GW_STR];
                #pragma unroll
                for (int mt = 0; mt < 4; mt++)
                    mma16(acc[mt][nt], af[mt], b0, b1);
            }
        }
    }

    #pragma unroll
    for (int mt = 0; mt < 4; mt++) {
        const int row = bm + wm * 64 + mt * 16 + g;
        #pragma unroll
        for (int nt = 0; nt < 4; nt++) {
            const int col = bn + wn * 32 + nt * 8 + 2 * c;
            const float b0 = bias[col], b1 = bias[col + 1];
            float v00 = fmaxf(acc[mt][nt][0] + b0, 0.0f);
            float v01 = fmaxf(acc[mt][nt][1] + b1, 0.0f);
            float v10 = fmaxf(acc[mt][nt][2] + b0, 0.0f);
            float v11 = fmaxf(acc[mt][nt][3] + b1, 0.0f);
            if (OUT_HALF) {
                uint32_t* Ch = (uint32_t*)Cout;
                Ch[(size_t)row * NP_ + (col >> 1)]       = h2pack(v00, v01);
                Ch[(size_t)(row + 8) * NP_ + (col >> 1)] = h2pack(v10, v11);
            } else {
                float* Cf = (float*)Cout;
                float2 a; a.x = v00; a.y = v01;
                float2 bb; bb.x = v10; bb.y = v11;
                *(float2*)(Cf + (size_t)row * D_ + col) = a;
                *(float2*)(Cf + (size_t)(row + 8) * D_ + col) = bb;
            }
        }
    }
}

__global__ void __launch_bounds__(256)
gemm_h_qkv(const uint32_t* __restrict__ xh,
           const float* __restrict__ Wq, const float* __restrict__ bq, uint32_t* __restrict__ Q,
           const float* __restrict__ Wk, const float* __restrict__ bk, uint32_t* __restrict__ K,
           const float* __restrict__ Wv, const float* __restrict__ bv, uint32_t* __restrict__ V)
{
    const float* W; const float* bias; uint32_t* C;
    if (blockIdx.z == 0)      { W = Wq; bias = bq; C = Q; }
    else if (blockIdx.z == 1) { W = Wk; bias = bk; C = K; }
    else                      { W = Wv; bias = bv; C = V; }
    gemm_h_body<1>(xh, W, bias, C, blockIdx.y * 128, blockIdx.x * 128);
}

__global__ void __launch_bounds__(256)
gemm_h_out(const uint32_t* __restrict__ Ah, const float* __restrict__ W,
           const float* __restrict__ bias, float* __restrict__ C)
{
    gemm_h_body<0>(Ah, W, bias, C, blockIdx.y * 128, blockIdx.x * 128);
}

// ================= flash attention: half in/out, ldmatrix fragments =========
// BM=64 q rows, BN=64 keys/tile, 128 threads (4 warps, 16m x 64n each).
// Qs/Ks/Vs natural [row][32 d-pairs], stride 36 uint32 (rows 144B, 16B-aligned).
#define AT_BM 64
#define HSTR 36

__global__ void __launch_bounds__(128, 4)
attn_h(const uint32_t* __restrict__ Qg, const uint32_t* __restrict__ Kg,
       const uint32_t* __restrict__ Vg, uint32_t* __restrict__ Og)
{
    __shared__ __align__(16) uint32_t Qs[AT_BM * HSTR];
    __shared__ __align__(16) uint32_t Ks[64 * HSTR];
    __shared__ __align__(16) uint32_t Vs[64 * HSTR];

    const int tid = threadIdx.x;
    const int lane = tid & 31;
    const int wid = tid >> 5;
    const int g = lane >> 2;   // 0..7
    const int c = lane & 3;    // 0..3
    const int qblk = blockIdx.x;
    const int h = blockIdx.y;
    const int b = blockIdx.z;

    // 1/sqrt(64) * log2(e), applied to Q in half
    const __half2 sc2 = __float2half2_rn(0.18033688f);

    // ---- stage Q (pure copy + hmul2 scale)
    {
        const size_t qrow0 = (size_t)b * S_ + qblk * AT_BM;
        #pragma unroll
        for (int it = 0; it < 4; it++) {
            int idx = tid + it * 128;      // 0..511
            int m = idx >> 3, ch = idx & 7;
            uint4 u = *(const uint4*)(Qg + (qrow0 + m) * NP_ + h * 32 + 4 * ch);
            u.x = hmul2u(u.x, sc2); u.y = hmul2u(u.y, sc2);
            u.z = hmul2u(u.z, sc2); u.w = hmul2u(u.w, sc2);
            *(uint4*)&Qs[m * HSTR + 4 * ch] = u;
        }
    }
    __syncthreads();

    // Q a-frags to registers (4 k-chunks of 16 d)
    uint32_t qf[4][4];
    {
        const int r0 = (wid * 16 + g) * HSTR;
        const int r1 = r0 + 8 * HSTR;
        #pragma unroll
        for (int kc = 0; kc < 4; kc++) {
            qf[kc][0] = Qs[r0 + 8 * kc + c];
            qf[kc][1] = Qs[r1 + 8 * kc + c];
            qf[kc][2] = Qs[r0 + 8 * kc + 4 + c];
            qf[kc][3] = Qs[r1 + 8 * kc + 4 + c];
        }
    }

    // ldmatrix per-thread base addresses
    const int j = lane >> 3, r = lane & 7;
    const uint32_t kbase = smem_u32(Ks) +
        ((((j >> 1) * 8 + r) * HSTR + (j & 1) * 4) << 2);
    const uint32_t vbase = smem_u32(Vs) +
        ((((j & 1) * 8 + r) * HSTR + (j >> 1) * 4) << 2);

    float o[8][4];
    #pragma unroll
    for (int nt = 0; nt < 8; nt++)
        #pragma unroll
        for (int jj = 0; jj < 4; jj++) o[nt][jj] = 0.0f;
    float m0 = -1e30f, m1 = -1e30f, l0 = 0.0f, l1 = 0.0f;

    const size_t kvrow0 = (size_t)b * S_;

    for (int t0 = 0; t0 < S_; t0 += 64) {
        __syncthreads();  // prior tile's ldmatrix reads done

        // ---- stage K and V: pure uint4 copies
        #pragma unroll
        for (int it = 0; it < 4; it++) {
            int idx = tid + it * 128;
            int n = idx >> 3, ch = idx & 7;
            size_t goff = (kvrow0 + t0 + n) * NP_ + h * 32 + 4 * ch;
            *(uint4*)&Ks[n * HSTR + 4 * ch] = *(const uint4*)(Kg + goff);
            *(uint4*)&Vs[n * HSTR + 4 * ch] = *(const uint4*)(Vg + goff);
        }
        __syncthreads();

        // ---- S = Q @ K^T via ldmatrix (non-trans) b-frags
        float sacc[8][4];
        #pragma unroll
        for (int nt = 0; nt < 8; nt++)
            #pragma unroll
            for (int jj = 0; jj < 4; jj++) sacc[nt][jj] = 0.0f;

        #pragma unroll
        for (int kc = 0; kc < 4; kc++) {
            #pragma unroll
            for (int np = 0; np < 4; np++) {
                uint32_t r0, r1, r2, r3;
                LDMX4(r0, r1, r2, r3, kbase + np * (16 * HSTR * 4) + kc * 32);
                mma16(sacc[2 * np],     qf[kc], r0, r1);
                mma16(sacc[2 * np + 1], qf[kc], r2, r3);
            }
        }

        // ---- online softmax (log2 domain); thread owns rows g and g+8
        float tm0 = -1e30f, tm1 = -1e30f;
        #pragma unroll
        for (int nt = 0; nt < 8; nt++) {
            tm0 = fmaxf(tm0, fmaxf(sacc[nt][0], sacc[nt][1]));
            tm1 = fmaxf(tm1, fmaxf(sacc[nt][2], sacc[nt][3]));
        }
        tm0 = fmaxf(tm0, __shfl_xor_sync(0xffffffff, tm0, 1));
        tm0 = fmaxf(tm0, __shfl_xor_sync(0xffffffff, tm0, 2));
        tm1 = fmaxf(tm1, __shfl_xor_sync(0xffffffff, tm1, 1));
        tm1 = fmaxf(tm1, __shfl_xor_sync(0xffffffff, tm1, 2));

        float mn0 = fmaxf(m0, tm0), mn1 = fmaxf(m1, tm1);
        float corr0 = exp2_fast(m0 - mn0), corr1 = exp2_fast(m1 - mn1);
        m0 = mn0; m1 = mn1;

        float rs0 = 0.0f, rs1 = 0.0f;
        #pragma unroll
        for (int nt = 0; nt < 8; nt++) {
            sacc[nt][0] = exp2_fast(sacc[nt][0] - m0);
            sacc[nt][1] = exp2_fast(sacc[nt][1] - m0);
            sacc[nt][2] = exp2_fast(sacc[nt][2] - m1);
            sacc[nt][3] = exp2_fast(sacc[nt][3] - m1);
            rs0 += sacc[nt][0] + sacc[nt][1];
            rs1 += sacc[nt][2] + sacc[nt][3];
        }
        rs0 += __shfl_xor_sync(0xffffffff, rs0, 1);
        rs0 += __shfl_xor_sync(0xffffffff, rs0, 2);
        rs1 += __shfl_xor_sync(0xffffffff, rs1, 1);
        rs1 += __shfl_xor_sync(0xffffffff, rs1, 2);
        l0 = l0 * corr0 + rs0;
        l1 = l1 * corr1 + rs1;
        #pragma unroll
        for (int nt = 0; nt < 8; nt++) {
            o[nt][0] *= corr0; o[nt][1] *= corr0;
            o[nt][2] *= corr1; o[nt][3] *= corr1;
        }

        // ---- O += P @ V via ldmatrix.trans b-frags; P packs from registers
        #pragma unroll
        for (int kc = 0; kc < 4; kc++) {
            uint32_t af[4];
            af[0] = h2pack(sacc[2 * kc][0], sacc[2 * kc][1]);
            af[1] = h2pack(sacc[2 * kc][2], sacc[2 * kc][3]);
            af[2] = h2pack(sacc[2 * kc + 1][0], sacc[2 * kc + 1][1]);
            af[3] = h2pack(sacc[2 * kc + 1][2], sacc[2 * kc + 1][3]);
            #pragma unroll
            for (int np = 0; np < 4; np++) {
                uint32_t r0, r1, r2, r3;
                LDMX4T(r0, r1, r2, r3, vbase + kc * (16 * HSTR * 4) + np * 32);
                mma16(o[2 * np],     af, r0, r1);
                mma16(o[2 * np + 1], af, r2, r3);
            }
        }
    }

    // ---- epilogue: half output pairs
    const float inv0 = 1.0f / l0, inv1 = 1.0f / l1;
    uint32_t* ob = Og + ((size_t)b * S_ + qblk * AT_BM + wid * 16 + g) * NP_ + h * 32;
    #pragma unroll
    for (int nt = 0; nt < 8; nt++) {
        ob[nt * 4 + c]            = h2pack(o[nt][0] * inv0, o[nt][1] * inv0);
        ob[8 * NP_ + nt * 4 + c]  = h2pack(o[nt][2] * inv1, o[nt][3] * inv1);
    }
}

// ---------------- launch ----------------
extern "C" void kernel_launch(void* const* d_in, const int* in_sizes, int n_in,
                              void* d_out, int out_size)
{
    const float* x  = (const float*)d_in[0];
    const float* Wq = (const float*)d_in[1];
    const float* bq = (const float*)d_in[2];
    const float* Wk = (const float*)d_in[3];
    const float* bk = (const float*)d_in[4];
    const float* Wv = (const float*)d_in[5];
    const float* bv = (const float*)d_in[6];
    const float* Wo = (const float*)d_in[7];
    const float* bo = (const float*)d_in[8];
    float* out = (float*)d_out;

    uint32_t *xh, *Qh, *Kh, *Vh, *Oh;
    cudaGetSymbolAddress((void**)&xh, g_xh);
    cudaGetSymbolAddress((void**)&Qh, g_qh);
    cudaGetSymbolAddress((void**)&Kh, g_kh);
    cudaGetSymbolAddress((void**)&Vh, g_vh);
    cudaGetSymbolAddress((void**)&Oh, g_oh);

    // x -> half pairs (B*S*D/8 = 524288 uint4 outputs)
    cvt_x<<<2048, 256>>>((const float4*)x, (uint4*)xh);

    dim3 qkv_grid(D_ / 128, (B_ * S_) / 128, 3);   // (4, 64, 3)
    gemm_h_qkv<<<qkv_grid, 256>>>(xh, Wq, bq, Qh, Wk, bk, Kh, Wv, bv, Vh);

    dim3 agrid(S_ / AT_BM, H_, B_);  // (64, 8, 2) = 1024 blocks
    attn_h<<<agrid, 128>>>(Qh, Kh, Vh, Oh);

    dim3 ogrid(D_ / 128, (B_ * S_) / 128);         // (4, 64)
    gemm_h_out<<<ogrid, 256>>>(Oh, Wo, bo, out);
}

// round 9
// speedup vs baseline: 9.5866x; 1.1604x over previous
#include <cuda_runtime.h>
#include <cuda_fp16.h>
#include <cstddef>
#include <cstdint>

// Problem constants
#define B_ 2
#define S_ 4096
#define D_ 512
#define H_ 8
#define DH_ 64
#define NP_ 256   // pairs per row (D_/2)

// ---------------- scratch (no allocation allowed) ----------------
__device__ __align__(16) uint32_t g_xh[(size_t)B_ * S_ * NP_];
__device__ __align__(16) uint32_t g_qh[(size_t)B_ * S_ * NP_];
__device__ __align__(16) uint32_t g_kh[(size_t)B_ * S_ * NP_];
__device__ __align__(16) uint32_t g_vh[(size_t)B_ * S_ * NP_];
__device__ __align__(16) uint32_t g_oh[(size_t)B_ * S_ * NP_];
// weights as k-pair-packed half: [4][256 kp][512 n] uint32
__device__ __align__(16) uint32_t g_wh[4][(size_t)NP_ * D_];

// ---------------- helpers ----------------
__device__ __forceinline__ uint32_t smem_u32(const void* p) {
    uint32_t a;
    asm("{ .reg .u64 t; cvta.to.shared.u64 t, %1; cvt.u32.u64 %0, t; }"
        : "=r"(a) : "l"(p));
    return a;
}
__device__ __forceinline__ uint32_t h2pack(float lo, float hi) {
    __half2 h = __floats2half2_rn(lo, hi);
    return *(uint32_t*)&h;
}
__device__ __forceinline__ uint32_t hmul2u(uint32_t a, __half2 s) {
    __half2 r = __hmul2(*(__half2*)&a, s);
    return *(uint32_t*)&r;
}
// exp2 on the MUFU pipe: 1 issue slot, ~2 ulp.
__device__ __forceinline__ float ex2a(float x) {
    float y;
    asm("ex2.approx.ftz.f32 %0, %1;" : "=f"(y) : "f"(x));
    return y;
}

// fp16 MMA: D(16x8) += A(16x16) * B(16x8), fp32 accum
__device__ __forceinline__ void mma16(float* d, const uint32_t* a,
                                      uint32_t b0, uint32_t b1) {
    asm volatile(
        "mma.sync.aligned.m16n8k16.row.col.f32.f16.f16.f32 "
        "{%0,%1,%2,%3}, {%4,%5,%6,%7}, {%8,%9}, {%0,%1,%2,%3};"
        : "+f"(d[0]), "+f"(d[1]), "+f"(d[2]), "+f"(d[3])
        : "r"(a[0]), "r"(a[1]), "r"(a[2]), "r"(a[3]), "r"(b0), "r"(b1));
}

#define LDMX4(r0, r1, r2, r3, addr)                                        \
    asm volatile("ldmatrix.sync.aligned.m8n8.x4.shared.b16 "               \
                 "{%0,%1,%2,%3}, [%4];"                                    \
                 : "=r"(r0), "=r"(r1), "=r"(r2), "=r"(r3) : "r"(addr))
#define LDMX4T(r0, r1, r2, r3, addr)                                       \
    asm volatile("ldmatrix.sync.aligned.m8n8.x4.trans.shared.b16 "         \
                 "{%0,%1,%2,%3}, [%4];"                                    \
                 : "=r"(r0), "=r"(r1), "=r"(r2), "=r"(r3) : "r"(addr))

// ================= x -> half pairs =================
__global__ void __launch_bounds__(256)
cvt_x(const float4* __restrict__ x, uint4* __restrict__ xh)
{
    size_t i = (size_t)blockIdx.x * 256 + threadIdx.x;
    float4 a = x[2 * i], b = x[2 * i + 1];
    uint4 o;
    o.x = h2pack(a.x, a.y); o.y = h2pack(a.z, a.w);
    o.z = h2pack(b.x, b.y); o.w = h2pack(b.z, b.w);
    xh[i] = o;
}

// ================= W -> k-pair-packed half: Whg[kp][n] = (W[2kp][n], W[2kp+1][n])
__global__ void __launch_bounds__(256)
cvt_w(const float* __restrict__ Wq, const float* __restrict__ Wk,
      const float* __restrict__ Wv, const float* __restrict__ Wo,
      uint32_t* __restrict__ Whg)
{
    const float* W;
    if (blockIdx.y == 0)      W = Wq;
    else if (blockIdx.y == 1) W = Wk;
    else if (blockIdx.y == 2) W = Wv;
    else                      W = Wo;
    size_t i = (size_t)blockIdx.x * 256 + threadIdx.x;  // kp*512 + n
    size_t kp = i >> 9, n = i & 511;
    float lo = W[(2 * kp) * D_ + n];
    float hi = W[(2 * kp + 1) * D_ + n];
    Whg[(size_t)blockIdx.y * NP_ * D_ + i] = h2pack(lo, hi);
}

// ================= fp16 GEMM: C = relu(Ah[M,512] @ W[512,512] + b) =========
// Block 128m x 128n, k-tile 32 (16 kp). 8 warps 2m x 4n, warp tile 64m x 32n.
#define GA_STR 20
#define GW_STR 136

template <int OUT_HALF>
__device__ __forceinline__ void gemm_h_body(
    const uint32_t* __restrict__ Ah_g,   // [M][256] half k-pairs
    const uint32_t* __restrict__ Wh_g,   // [256 kp][512 n] half k-pairs
    const float* __restrict__ bias,
    void* __restrict__ Cout,
    int bm, int bn)
{
    __shared__ __align__(16) uint32_t Ah[128 * GA_STR];
    __shared__ __align__(16) uint32_t Wh[16 * GW_STR];

    const int tid = threadIdx.x;
    const int lane = tid & 31;
    const int wid = tid >> 5;
    const int wm = wid >> 2;
    const int wn = wid & 3;
    const int g = lane >> 2;
    const int c = lane & 3;

    float acc[4][4][4];
    #pragma unroll
    for (int mt = 0; mt < 4; mt++)
        #pragma unroll
        for (int nt = 0; nt < 4; nt++)
            #pragma unroll
            for (int j = 0; j < 4; j++) acc[mt][nt][j] = 0.0f;

    uint4 pa[2], pw[2];
    #pragma unroll
    for (int i = 0; i < 2; i++) {
        int idx = tid + i * 256;
        int m = idx >> 2, ch = idx & 3;
        pa[i] = *(const uint4*)(Ah_g + (size_t)(bm + m) * NP_ + 4 * ch);
        int kp = idx >> 5, n4 = idx & 31;
        pw[i] = *(const uint4*)(Wh_g + (size_t)kp * D_ + bn + 4 * n4);
    }

    for (int kt = 0; kt < 16; kt++) {
        __syncthreads();
        #pragma unroll
        for (int i = 0; i < 2; i++) {
            int idx = tid + i * 256;
            int m = idx >> 2, ch = idx & 3;
            *(uint4*)&Ah[m * GA_STR + 4 * ch] = pa[i];
            int kp = idx >> 5, n4 = idx & 31;
            *(uint4*)&Wh[kp * GW_STR + 4 * n4] = pw[i];
        }
        __syncthreads();

        if (kt < 15) {
            #pragma unroll
            for (int i = 0; i < 2; i++) {
                int idx = tid + i * 256;
                int m = idx >> 2, ch = idx & 3;
                pa[i] = *(const uint4*)(Ah_g + (size_t)(bm + m) * NP_ +
                                        (kt + 1) * 16 + 4 * ch);
                int kp = idx >> 5, n4 = idx & 31;
                pw[i] = *(const uint4*)(Wh_g + (size_t)((kt + 1) * 16 + kp) * D_ +
                                        bn + 4 * n4);
            }
        }

        #pragma unroll
        for (int kc = 0; kc < 2; kc++) {
            uint32_t af[4][4];
            #pragma unroll
            for (int mt = 0; mt < 4; mt++) {
                int base = (wm * 64 + mt * 16 + g) * GA_STR + kc * 8 + c;
                af[mt][0] = Ah[base];
                af[mt][1] = Ah[base + 8 * GA_STR];
                af[mt][2] = Ah[base + 4];
                af[mt][3] = Ah[base + 8 * GA_STR + 4];
            }
            #pragma unroll
            for (int nt = 0; nt < 4; nt++) {
                int rb = (kc * 8 + c) * GW_STR + wn * 32 + nt * 8 + g;
                uint32_t b0 = Wh[rb];
                uint32_t b1 = Wh[rb + 4 * GW_STR];
                #pragma unroll
                for (int mt = 0; mt < 4; mt++)
                    mma16(acc[mt][nt], af[mt], b0, b1);
            }
        }
    }

    #pragma unroll
    for (int mt = 0; mt < 4; mt++) {
        const int row = bm + wm * 64 + mt * 16 + g;
        #pragma unroll
        for (int nt = 0; nt < 4; nt++) {
            const int col = bn + wn * 32 + nt * 8 + 2 * c;
            const float b0 = bias[col], b1 = bias[col + 1];
            float v00 = fmaxf(acc[mt][nt][0] + b0, 0.0f);
            float v01 = fmaxf(acc[mt][nt][1] + b1, 0.0f);
            float v10 = fmaxf(acc[mt][nt][2] + b0, 0.0f);
            float v11 = fmaxf(acc[mt][nt][3] + b1, 0.0f);
            if (OUT_HALF) {
                uint32_t* Ch = (uint32_t*)Cout;
                Ch[(size_t)row * NP_ + (col >> 1)]       = h2pack(v00, v01);
                Ch[(size_t)(row + 8) * NP_ + (col >> 1)] = h2pack(v10, v11);
            } else {
                float* Cf = (float*)Cout;
                float2 a; a.x = v00; a.y = v01;
                float2 bb; bb.x = v10; bb.y = v11;
                *(float2*)(Cf + (size_t)row * D_ + col) = a;
                *(float2*)(Cf + (size_t)(row + 8) * D_ + col) = bb;
            }
        }
    }
}

__global__ void __launch_bounds__(256)
gemm_h_qkv(const uint32_t* __restrict__ xh, const uint32_t* __restrict__ Whg,
           const float* __restrict__ bq, uint32_t* __restrict__ Q,
           const float* __restrict__ bk, uint32_t* __restrict__ K,
           const float* __restrict__ bv, uint32_t* __restrict__ V)
{
    const float* bias; uint32_t* C;
    if (blockIdx.z == 0)      { bias = bq; C = Q; }
    else if (blockIdx.z == 1) { bias = bk; C = K; }
    else                      { bias = bv; C = V; }
    gemm_h_body<1>(xh, Whg + (size_t)blockIdx.z * NP_ * D_, bias, C,
                   blockIdx.y * 128, blockIdx.x * 128);
}

__global__ void __launch_bounds__(256)
gemm_h_out(const uint32_t* __restrict__ Ah, const uint32_t* __restrict__ Whg,
           const float* __restrict__ bias, float* __restrict__ C)
{
    gemm_h_body<0>(Ah, Whg + (size_t)3 * NP_ * D_, bias, C,
                   blockIdx.y * 128, blockIdx.x * 128);
}

// ================= flash attention: half in/out, ldmatrix, MUFU exp =========
#define AT_BM 64
#define HSTR 36

__global__ void __launch_bounds__(128, 4)
attn_h(const uint32_t* __restrict__ Qg, const uint32_t* __restrict__ Kg,
       const uint32_t* __restrict__ Vg, uint32_t* __restrict__ Og)
{
    __shared__ __align__(16) uint32_t Qs[AT_BM * HSTR];
    __shared__ __align__(16) uint32_t Ks[64 * HSTR];
    __shared__ __align__(16) uint32_t Vs[64 * HSTR];

    const int tid = threadIdx.x;
    const int lane = tid & 31;
    const int wid = tid >> 5;
    const int g = lane >> 2;   // 0..7
    const int c = lane & 3;    // 0..3
    const int qblk = blockIdx.x;
    const int h = blockIdx.y;
    const int b = blockIdx.z;

    const __half2 sc2 = __float2half2_rn(0.18033688f);  // (1/8)*log2(e)

    // ---- stage Q (pure copy + hmul2 scale)
    {
        const size_t qrow0 = (size_t)b * S_ + qblk * AT_BM;
        #pragma unroll
        for (int it = 0; it < 4; it++) {
            int idx = tid + it * 128;
            int m = idx >> 3, ch = idx & 7;
            uint4 u = *(const uint4*)(Qg + (qrow0 + m) * NP_ + h * 32 + 4 * ch);
            u.x = hmul2u(u.x, sc2); u.y = hmul2u(u.y, sc2);
            u.z = hmul2u(u.z, sc2); u.w = hmul2u(u.w, sc2);
            *(uint4*)&Qs[m * HSTR + 4 * ch] = u;
        }
    }
    __syncthreads();

    // Q a-frags to registers (4 k-chunks of 16 d)
    uint32_t qf[4][4];
    {
        const int r0 = (wid * 16 + g) * HSTR;
        const int r1 = r0 + 8 * HSTR;
        #pragma unroll
        for (int kc = 0; kc < 4; kc++) {
            qf[kc][0] = Qs[r0 + 8 * kc + c];
            qf[kc][1] = Qs[r1 + 8 * kc + c];
            qf[kc][2] = Qs[r0 + 8 * kc + 4 + c];
            qf[kc][3] = Qs[r1 + 8 * kc + 4 + c];
        }
    }

    // ldmatrix per-thread base addresses
    const int j = lane >> 3, r = lane & 7;
    const uint32_t kbase = smem_u32(Ks) +
        ((((j >> 1) * 8 + r) * HSTR + (j & 1) * 4) << 2);
    const uint32_t vbase = smem_u32(Vs) +
        ((((j & 1) * 8 + r) * HSTR + (j >> 1) * 4) << 2);

    float o[8][4];
    #pragma unroll
    for (int nt = 0; nt < 8; nt++)
        #pragma unroll
        for (int jj = 0; jj < 4; jj++) o[nt][jj] = 0.0f;
    float m0 = -1e30f, m1 = -1e30f, l0 = 0.0f, l1 = 0.0f;

    const size_t kvrow0 = (size_t)b * S_;

    for (int t0 = 0; t0 < S_; t0 += 64) {
        __syncthreads();

        #pragma unroll
        for (int it = 0; it < 4; it++) {
            int idx = tid + it * 128;
            int n = idx >> 3, ch = idx & 7;
            size_t goff = (kvrow0 + t0 + n) * NP_ + h * 32 + 4 * ch;
            *(uint4*)&Ks[n * HSTR + 4 * ch] = *(const uint4*)(Kg + goff);
            *(uint4*)&Vs[n * HSTR + 4 * ch] = *(const uint4*)(Vg + goff);
        }
        __syncthreads();

        // ---- S = Q @ K^T
        float sacc[8][4];
        #pragma unroll
        for (int nt = 0; nt < 8; nt++)
            #pragma unroll
            for (int jj = 0; jj < 4; jj++) sacc[nt][jj] = 0.0f;

        #pragma unroll
        for (int kc = 0; kc < 4; kc++) {
            #pragma unroll
            for (int np = 0; np < 4; np++) {
                uint32_t r0, r1, r2, r3;
                LDMX4(r0, r1, r2, r3, kbase + np * (16 * HSTR * 4) + kc * 32);
                mma16(sacc[2 * np],     qf[kc], r0, r1);
                mma16(sacc[2 * np + 1], qf[kc], r2, r3);
            }
        }

        // ---- online softmax (log2 domain), exp on MUFU
        float tm0 = -1e30f, tm1 = -1e30f;
        #pragma unroll
        for (int nt = 0; nt < 8; nt++) {
            tm0 = fmaxf(tm0, fmaxf(sacc[nt][0], sacc[nt][1]));
            tm1 = fmaxf(tm1, fmaxf(sacc[nt][2], sacc[nt][3]));
        }
        tm0 = fmaxf(tm0, __shfl_xor_sync(0xffffffff, tm0, 1));
        tm0 = fmaxf(tm0, __shfl_xor_sync(0xffffffff, tm0, 2));
        tm1 = fmaxf(tm1, __shfl_xor_sync(0xffffffff, tm1, 1));
        tm1 = fmaxf(tm1, __shfl_xor_sync(0xffffffff, tm1, 2));

        float mn0 = fmaxf(m0, tm0), mn1 = fmaxf(m1, tm1);
        float corr0 = ex2a(m0 - mn0), corr1 = ex2a(m1 - mn1);
        m0 = mn0; m1 = mn1;

        float rs0 = 0.0f, rs1 = 0.0f;
        #pragma unroll
        for (int nt = 0; nt < 8; nt++) {
            sacc[nt][0] = ex2a(sacc[nt][0] - m0);
            sacc[nt][1] = ex2a(sacc[nt][1] - m0);
            sacc[nt][2] = ex2a(sacc[nt][2] - m1);
            sacc[nt][3] = ex2a(sacc[nt][3] - m1);
            rs0 += sacc[nt][0] + sacc[nt][1];
            rs1 += sacc[nt][2] + sacc[nt][3];
        }
        rs0 += __shfl_xor_sync(0xffffffff, rs0, 1);
        rs0 += __shfl_xor_sync(0xffffffff, rs0, 2);
        rs1 += __shfl_xor_sync(0xffffffff, rs1, 1);
        rs1 += __shfl_xor_sync(0xffffffff, rs1, 2);
        l0 = l0 * corr0 + rs0;
        l1 = l1 * corr1 + rs1;
        #pragma unroll
        for (int nt = 0; nt < 8; nt++) {
            o[nt][0] *= corr0; o[nt][1] *= corr0;
            o[nt][2] *= corr1; o[nt][3] *= corr1;
        }

        // ---- O += P @ V via ldmatrix.trans
        #pragma unroll
        for (int kc = 0; kc < 4; kc++) {
            uint32_t af[4];
            af[0] = h2pack(sacc[2 * kc][0], sacc[2 * kc][1]);
            af[1] = h2pack(sacc[2 * kc][2], sacc[2 * kc][3]);
            af[2] = h2pack(sacc[2 * kc + 1][0], sacc[2 * kc + 1][1]);
            af[3] = h2pack(sacc[2 * kc + 1][2], sacc[2 * kc + 1][3]);
            #pragma unroll
            for (int np = 0; np < 4; np++) {
                uint32_t r0, r1, r2, r3;
                LDMX4T(r0, r1, r2, r3, vbase + kc * (16 * HSTR * 4) + np * 32);
                mma16(o[2 * np],     af, r0, r1);
                mma16(o[2 * np + 1], af, r2, r3);
            }
        }
    }

    // ---- epilogue: half output pairs
    const float inv0 = 1.0f / l0, inv1 = 1.0f / l1;
    uint32_t* ob = Og + ((size_t)b * S_ + qblk * AT_BM + wid * 16 + g) * NP_ + h * 32;
    #pragma unroll
    for (int nt = 0; nt < 8; nt++) {
        ob[nt * 4 + c]            = h2pack(o[nt][0] * inv0, o[nt][1] * inv0);
        ob[8 * NP_ + nt * 4 + c]  = h2pack(o[nt][2] * inv1, o[nt][3] * inv1);
    }
}

// ---------------- launch ----------------
extern "C" void kernel_launch(void* const* d_in, const int* in_sizes, int n_in,
                              void* d_out, int out_size)
{
    const float* x  = (const float*)d_in[0];
    const float* Wq = (const float*)d_in[1];
    const float* bq = (const float*)d_in[2];
    const float* Wk = (const float*)d_in[3];
    const float* bk = (const float*)d_in[4];
    const float* Wv = (const float*)d_in[5];
    const float* bv = (const float*)d_in[6];
    const float* Wo = (const float*)d_in[7];
    const float* bo = (const float*)d_in[8];
    float* out = (float*)d_out;

    uint32_t *xh, *Qh, *Kh, *Vh, *Oh, *Whg;
    cudaGetSymbolAddress((void**)&xh, g_xh);
    cudaGetSymbolAddress((void**)&Qh, g_qh);
    cudaGetSymbolAddress((void**)&Kh, g_kh);
    cudaGetSymbolAddress((void**)&Vh, g_vh);
    cudaGetSymbolAddress((void**)&Oh, g_oh);
    cudaGetSymbolAddress((void**)&Whg, g_wh);

    cvt_x<<<2048, 256>>>((const float4*)x, (uint4*)xh);
    dim3 wgrid(512, 4);   // 131072 uint32 per W
    cvt_w<<<wgrid, 256>>>(Wq, Wk, Wv, Wo, Whg);

    dim3 qkv_grid(D_ / 128, (B_ * S_) / 128, 3);   // (4, 64, 3)
    gemm_h_qkv<<<qkv_grid, 256>>>(xh, Whg, bq, Qh, bk, Kh, bv, Vh);

    dim3 agrid(S_ / AT_BM, H_, B_);  // (64, 8, 2) = 1024 blocks
    attn_h<<<agrid, 128>>>(Qh, Kh, Vh, Oh);

    dim3 ogrid(D_ / 128, (B_ * S_) / 128);         // (4, 64)
    gemm_h_out<<<ogrid, 256>>>(Oh, Whg, bo, out);
}